// round 3
// baseline (speedup 1.0000x reference)
#include <cuda_runtime.h>

#define BB    8
#define CIN   67
#define CINP  68          // padded (row 67 zeroed)
#define C2    128
#define CO    64
#define NN    16384
#define EPSV  1e-5f
#define TN    128         // n-tile
#define SPLITS 32         // pass1 splits per batch
#define NPART (BB * SPLITS)      // 256 pass1 blocks
#define TILES_PER_SPLIT 4        // 512 n per split / TN

// ---------------- device scratch (no allocations allowed) ----------------
__device__ __align__(16) float g_Wq[CINP][C2];   // folded, transposed: [k][o]
__device__ __align__(16) float g_Wk[CINP][C2];
__device__ __align__(16) float g_Wv[CINP][C2];
__device__ __align__(16) float g_bq[C2];
__device__ __align__(16) float g_bk[C2];
__device__ __align__(16) float g_bv[C2];
__device__ __align__(16) float g_Wf[CO][C2];     // folded, natural: [o][d]
__device__ __align__(16) float g_bf[CO];
__device__ __align__(16) float g_MT[BB][C2][CO]; // MT[b][c][o] = M[b][o][c]
__device__ __align__(16) float g_kvpart[NPART][C2 * C2];

// ---------------- prep: fold BN into weights/biases ----------------
__global__ void prep_kernel(const float* __restrict__ Wq, const float* __restrict__ Wk,
                            const float* __restrict__ Wv, const float* __restrict__ Wf,
                            const float* __restrict__ bnq, const float* __restrict__ bnk,
                            const float* __restrict__ bnv, const float* __restrict__ bnf) {
    __shared__ float sq[C2], sk[C2], sv[C2], sf[CO];
    int tid = threadIdx.x;
    if (tid < C2) {
        float s;
        s = bnq[tid] * rsqrtf(bnq[3 * C2 + tid] + EPSV);
        sq[tid] = s; g_bq[tid] = bnq[C2 + tid] - bnq[2 * C2 + tid] * s;
        s = bnk[tid] * rsqrtf(bnk[3 * C2 + tid] + EPSV);
        sk[tid] = s; g_bk[tid] = bnk[C2 + tid] - bnk[2 * C2 + tid] * s;
        s = bnv[tid] * rsqrtf(bnv[3 * C2 + tid] + EPSV);
        sv[tid] = s; g_bv[tid] = bnv[C2 + tid] - bnv[2 * C2 + tid] * s;
    }
    if (tid < CO) {
        float s = bnf[tid] * rsqrtf(bnf[3 * CO + tid] + EPSV);
        sf[tid] = s; g_bf[tid] = bnf[CO + tid] - bnf[2 * CO + tid] * s;
    }
    __syncthreads();
    for (int idx = tid; idx < CINP * C2; idx += blockDim.x) {
        int k = idx >> 7, o = idx & 127;
        float wq = 0.f, wk = 0.f, wv = 0.f;
        if (k < CIN) {
            wq = Wq[o * CIN + k] * sq[o];
            wk = Wk[o * CIN + k] * sk[o];
            wv = Wv[o * CIN + k] * sv[o];
        }
        g_Wq[k][o] = wq; g_Wk[k][o] = wk; g_Wv[k][o] = wv;
    }
    for (int idx = tid; idx < CO * C2; idx += blockDim.x) {
        int o = idx >> 7;
        g_Wf[0][idx] = Wf[idx] * sf[o];
    }
}

// ---------------- shared GEMM micro-kernel: C[128][TN] = W(128x68) @ xs(68xTN) ----------------
// W is [CINP][C2] (k-major, transposed). Output ReLU(acc + bias).
// TRANS=true  -> store outT[n][o] (stride C2)   (for ksT / vsT)
// TRANS=false -> store out[o][n]  (stride TN)   (for qs)
template <bool TRANS>
__device__ __forceinline__ void gemm_wx(const float* __restrict__ W,
                                        const float* __restrict__ xs,
                                        const float* __restrict__ gbias,
                                        float* __restrict__ osm,
                                        int r0, int c0) {
    float acc[8][8];
#pragma unroll
    for (int i = 0; i < 8; ++i)
#pragma unroll
        for (int j = 0; j < 8; ++j) acc[i][j] = 0.f;

#pragma unroll 4
    for (int k = 0; k < CINP; ++k) {
        const float4 a0 = *reinterpret_cast<const float4*>(W + k * C2 + r0);
        const float4 a1 = *reinterpret_cast<const float4*>(W + k * C2 + r0 + 4);
        const float4 b0 = *reinterpret_cast<const float4*>(xs + k * TN + c0);
        const float4 b1 = *reinterpret_cast<const float4*>(xs + k * TN + c0 + 4);
        const float av[8] = {a0.x, a0.y, a0.z, a0.w, a1.x, a1.y, a1.z, a1.w};
        const float bv[8] = {b0.x, b0.y, b0.z, b0.w, b1.x, b1.y, b1.z, b1.w};
#pragma unroll
        for (int i = 0; i < 8; ++i)
#pragma unroll
            for (int j = 0; j < 8; ++j) acc[i][j] = fmaf(av[i], bv[j], acc[i][j]);
    }
    float bias[8];
#pragma unroll
    for (int i = 0; i < 8; ++i) bias[i] = gbias[r0 + i];

    if (TRANS) {
#pragma unroll
        for (int j = 0; j < 8; ++j) {
            float4 lo, hi;
            lo.x = fmaxf(acc[0][j] + bias[0], 0.f);
            lo.y = fmaxf(acc[1][j] + bias[1], 0.f);
            lo.z = fmaxf(acc[2][j] + bias[2], 0.f);
            lo.w = fmaxf(acc[3][j] + bias[3], 0.f);
            hi.x = fmaxf(acc[4][j] + bias[4], 0.f);
            hi.y = fmaxf(acc[5][j] + bias[5], 0.f);
            hi.z = fmaxf(acc[6][j] + bias[6], 0.f);
            hi.w = fmaxf(acc[7][j] + bias[7], 0.f);
            *reinterpret_cast<float4*>(osm + (c0 + j) * C2 + r0)     = lo;
            *reinterpret_cast<float4*>(osm + (c0 + j) * C2 + r0 + 4) = hi;
        }
    } else {
#pragma unroll
        for (int i = 0; i < 8; ++i) {
            float4 lo, hi;
            lo.x = fmaxf(acc[i][0] + bias[i], 0.f);
            lo.y = fmaxf(acc[i][1] + bias[i], 0.f);
            lo.z = fmaxf(acc[i][2] + bias[i], 0.f);
            lo.w = fmaxf(acc[i][3] + bias[i], 0.f);
            hi.x = fmaxf(acc[i][4] + bias[i], 0.f);
            hi.y = fmaxf(acc[i][5] + bias[i], 0.f);
            hi.z = fmaxf(acc[i][6] + bias[i], 0.f);
            hi.w = fmaxf(acc[i][7] + bias[i], 0.f);
            *reinterpret_cast<float4*>(osm + (r0 + i) * TN + c0)     = lo;
            *reinterpret_cast<float4*>(osm + (r0 + i) * TN + c0 + 4) = hi;
        }
    }
}

// ---------------- pass 1: k,v GEMMs + kv outer-product accumulation ----------------
// smem: xs[CINP][TN] | ksT[TN][C2] | vsT[TN][C2]
__global__ void __launch_bounds__(256, 1)
pass1_kernel(const float* __restrict__ x) {
    extern __shared__ float smem[];
    float* xs  = smem;                      // CINP*TN
    float* ksT = smem + CINP * TN;          // TN*C2
    float* vsT = ksT + TN * C2;             // TN*C2

    const int tid = threadIdx.x;
    const int tx = tid & 15, ty = tid >> 4;
    const int r0 = ty * 8, c0 = tx * 8;
    const int b = blockIdx.x >> 5, split = blockIdx.x & 31;
    const float* xb = x + (size_t)b * CIN * NN;

    float kvacc[8][8];
#pragma unroll
    for (int i = 0; i < 8; ++i)
#pragma unroll
        for (int j = 0; j < 8; ++j) kvacc[i][j] = 0.f;

    if (tid < TN) xs[CIN * TN + tid] = 0.f;   // zero padded row 67

    for (int t = 0; t < TILES_PER_SPLIT; ++t) {
        const int n0 = split * (TILES_PER_SPLIT * TN) + t * TN;
        for (int idx = tid; idx < CIN * TN; idx += 256) {
            int k = idx >> 7, n = idx & 127;
            xs[idx] = xb[k * NN + n0 + n];
        }
        __syncthreads();

        gemm_wx<true>(&g_Wk[0][0], xs, g_bk, ksT, r0, c0);
        gemm_wx<true>(&g_Wv[0][0], xs, g_bv, vsT, r0, c0);
        __syncthreads();

        // kv[c][d] += sum_n k[c][n] * v[d][n]
        const float4* k4 = reinterpret_cast<const float4*>(ksT);
        const float4* v4 = reinterpret_cast<const float4*>(vsT);
        const int ra = r0 >> 2, cb = c0 >> 2;
#pragma unroll 4
        for (int n = 0; n < TN; ++n) {
            const float4 a0 = k4[n * 32 + ra];
            const float4 a1 = k4[n * 32 + ra + 1];
            const float4 b0 = v4[n * 32 + cb];
            const float4 b1 = v4[n * 32 + cb + 1];
            const float av[8] = {a0.x, a0.y, a0.z, a0.w, a1.x, a1.y, a1.z, a1.w};
            const float bv[8] = {b0.x, b0.y, b0.z, b0.w, b1.x, b1.y, b1.z, b1.w};
#pragma unroll
            for (int i = 0; i < 8; ++i)
#pragma unroll
                for (int j = 0; j < 8; ++j) kvacc[i][j] = fmaf(av[i], bv[j], kvacc[i][j]);
        }
        __syncthreads();   // ksT/vsT reads done before next tile overwrites
    }

    float* part = g_kvpart[blockIdx.x];
#pragma unroll
    for (int i = 0; i < 8; ++i) {
        float4 lo = {kvacc[i][0], kvacc[i][1], kvacc[i][2], kvacc[i][3]};
        float4 hi = {kvacc[i][4], kvacc[i][5], kvacc[i][6], kvacc[i][7]};
        *reinterpret_cast<float4*>(part + (r0 + i) * C2 + c0)     = lo;
        *reinterpret_cast<float4*>(part + (r0 + i) * C2 + c0 + 4) = hi;
    }
}

// ---------------- reduce kv partials + form MT[b][c][o] = sum_d Wf'[o][d]*kv[c][d] ----------------
__global__ void mkernel(void) {
    extern __shared__ float kvs[];   // C2*C2
    const int b = blockIdx.x, tid = threadIdx.x;
    for (int idx = tid; idx < C2 * C2; idx += 256) {
        float s = 0.f;
#pragma unroll
        for (int p = 0; p < SPLITS; ++p) s += g_kvpart[b * SPLITS + p][idx];
        kvs[idx] = s;
    }
    __syncthreads();

    const int tx = tid & 15, ty = tid >> 4;
    const int o0 = ty * 4, c0 = tx * 8;
    float acc[4][8];
#pragma unroll
    for (int i = 0; i < 4; ++i)
#pragma unroll
        for (int j = 0; j < 8; ++j) acc[i][j] = 0.f;

    for (int d = 0; d < C2; ++d) {
        float a[4], bv[8];
#pragma unroll
        for (int i = 0; i < 4; ++i) a[i] = g_Wf[o0 + i][d];
#pragma unroll
        for (int j = 0; j < 8; ++j) bv[j] = kvs[(c0 + j) * C2 + d];
#pragma unroll
        for (int i = 0; i < 4; ++i)
#pragma unroll
            for (int j = 0; j < 8; ++j) acc[i][j] = fmaf(a[i], bv[j], acc[i][j]);
    }
#pragma unroll
    for (int j = 0; j < 8; ++j) {
        float4 v = {acc[0][j], acc[1][j], acc[2][j], acc[3][j]};
        *reinterpret_cast<float4*>(&g_MT[b][c0 + j][o0]) = v;
    }
}

// ---------------- pass 2: q GEMM + out = relu(M[b] @ q + bf) ----------------
// smem: xs[CINP][TN] | qs[C2][TN]
__global__ void __launch_bounds__(256, 2)
pass2_kernel(const float* __restrict__ x, float* __restrict__ out) {
    extern __shared__ float smem[];
    float* xs = smem;                 // CINP*TN
    float* qs = smem + CINP * TN;     // C2*TN

    const int tid = threadIdx.x;
    const int tx = tid & 15, ty = tid >> 4;
    const int b = blockIdx.x >> 7, t = blockIdx.x & 127;
    const int n0 = t * TN;
    const float* xb = x + (size_t)b * CIN * NN;

    if (tid < TN) xs[CIN * TN + tid] = 0.f;
    for (int idx = tid; idx < CIN * TN; idx += 256) {
        int k = idx >> 7, n = idx & 127;
        xs[idx] = xb[k * NN + n0 + n];
    }
    __syncthreads();

    gemm_wx<false>(&g_Wq[0][0], xs, g_bq, qs, ty * 8, tx * 8);
    __syncthreads();

    // y[o][n] = sum_c MT[b][c][o] * q[c][n]
    const int o0 = ty * 4, nn0 = tx * 8;
    float acc[4][8];
#pragma unroll
    for (int i = 0; i < 4; ++i)
#pragma unroll
        for (int j = 0; j < 8; ++j) acc[i][j] = 0.f;

#pragma unroll 4
    for (int c = 0; c < C2; ++c) {
        const float4 a  = *reinterpret_cast<const float4*>(&g_MT[b][c][o0]);
        const float4 b0 = *reinterpret_cast<const float4*>(qs + c * TN + nn0);
        const float4 b1 = *reinterpret_cast<const float4*>(qs + c * TN + nn0 + 4);
        const float av[4] = {a.x, a.y, a.z, a.w};
        const float bv[8] = {b0.x, b0.y, b0.z, b0.w, b1.x, b1.y, b1.z, b1.w};
#pragma unroll
        for (int i = 0; i < 4; ++i)
#pragma unroll
            for (int j = 0; j < 8; ++j) acc[i][j] = fmaf(av[i], bv[j], acc[i][j]);
    }

#pragma unroll
    for (int i = 0; i < 4; ++i) {
        const int o = o0 + i;
        const float bias = g_bf[o];
        float4 lo, hi;
        lo.x = fmaxf(acc[i][0] + bias, 0.f);
        lo.y = fmaxf(acc[i][1] + bias, 0.f);
        lo.z = fmaxf(acc[i][2] + bias, 0.f);
        lo.w = fmaxf(acc[i][3] + bias, 0.f);
        hi.x = fmaxf(acc[i][4] + bias, 0.f);
        hi.y = fmaxf(acc[i][5] + bias, 0.f);
        hi.z = fmaxf(acc[i][6] + bias, 0.f);
        hi.w = fmaxf(acc[i][7] + bias, 0.f);
        float* op = out + ((size_t)(b * CO + o)) * NN + n0 + nn0;
        *reinterpret_cast<float4*>(op)     = lo;
        *reinterpret_cast<float4*>(op + 4) = hi;
    }
}

// ---------------- launch ----------------
extern "C" void kernel_launch(void* const* d_in, const int* in_sizes, int n_in,
                              void* d_out, int out_size) {
    const float* x   = (const float*)d_in[0];
    const float* Wq  = (const float*)d_in[1];
    const float* Wk  = (const float*)d_in[2];
    const float* Wv  = (const float*)d_in[3];
    const float* Wf  = (const float*)d_in[4];
    const float* bnq = (const float*)d_in[5];
    const float* bnk = (const float*)d_in[6];
    const float* bnv = (const float*)d_in[7];
    const float* bnf = (const float*)d_in[8];
    float* out = (float*)d_out;

    const int SMEM_P1 = (CINP * TN + 2 * TN * C2) * (int)sizeof(float);   // 165,888 B
    const int SMEM_P2 = (CINP * TN + C2 * TN) * (int)sizeof(float);       // 100,352 B
    const int SMEM_MK = C2 * C2 * (int)sizeof(float);                     //  65,536 B

    cudaFuncSetAttribute(pass1_kernel, cudaFuncAttributeMaxDynamicSharedMemorySize, SMEM_P1);
    cudaFuncSetAttribute(pass2_kernel, cudaFuncAttributeMaxDynamicSharedMemorySize, SMEM_P2);
    cudaFuncSetAttribute(mkernel,      cudaFuncAttributeMaxDynamicSharedMemorySize, SMEM_MK);

    prep_kernel<<<1, 256>>>(Wq, Wk, Wv, Wf, bnq, bnk, bnv, bnf);
    pass1_kernel<<<NPART, 256, SMEM_P1>>>(x);
    mkernel<<<BB, 256, SMEM_MK>>>();
    pass2_kernel<<<BB * (NN / TN), 256, SMEM_P2>>>(x, out);
}

// round 6
// speedup vs baseline: 1.4675x; 1.4675x over previous
#include <cuda_runtime.h>
#include <cuda_fp16.h>
#include <mma.h>
#include <cstdint>

using namespace nvcuda;

#define BB 8
#define CIN 67
#define C2 128
#define CO 64
#define NN 16384
#define EPSV 1e-5f

#define KP 80        // padded K for x GEMMs (67 data + bias row 67 + zeros)
#define X_LD 88      // xh / weight smem leading dim (halfs)
#define H_LD 136     // k/v/q f16 smem leading dim
#define S_LD 132     // f32 scratch leading dim

// pass1 smem byte offsets
#define P1_XH  0
#define P1_WK  22528
#define P1_WV  45056
#define P1_KF  67584
#define P1_VF  102400
#define P1_SCR 137216
#define P1_TOTAL 204800
// pass2 smem byte offsets
#define P2_XH  0
#define P2_WQ  22528
#define P2_QH  45056
#define P2_MH  79872
#define P2_SCR 97280
#define P2_TOTAL 164864

// ---------------- device scratch ----------------
__device__ __half g_Wqh[C2 * X_LD];   // folded, [o][k] k<67 data, k==67 bias, else 0
__device__ __half g_Wkh[C2 * X_LD];
__device__ __half g_Wvh[C2 * X_LD];
__device__ float g_Wf[CO][C2];
__device__ float g_bf[CO];
__device__ float g_M[BB][CO][C2];            // (Wf . kv^T) / 64
__device__ float g_kvpart[128][C2 * C2];     // per-CTA kv partials [c][d]

// ---------------- prep: fold BN into weights, pack f16, bias row trick ----------------
__global__ void prep_kernel(const float* __restrict__ Wq, const float* __restrict__ Wk,
                            const float* __restrict__ Wv, const float* __restrict__ Wf,
                            const float* __restrict__ bnq, const float* __restrict__ bnk,
                            const float* __restrict__ bnv, const float* __restrict__ bnf) {
    __shared__ float sq[C2], sk[C2], sv[C2], shq[C2], shk[C2], shv[C2], sf[CO];
    int tid = threadIdx.x;
    if (tid < C2) {
        float s;
        s = bnq[tid] * rsqrtf(bnq[3 * C2 + tid] + EPSV); sq[tid] = s; shq[tid] = bnq[C2 + tid] - bnq[2 * C2 + tid] * s;
        s = bnk[tid] * rsqrtf(bnk[3 * C2 + tid] + EPSV); sk[tid] = s; shk[tid] = bnk[C2 + tid] - bnk[2 * C2 + tid] * s;
        s = bnv[tid] * rsqrtf(bnv[3 * C2 + tid] + EPSV); sv[tid] = s; shv[tid] = bnv[C2 + tid] - bnv[2 * C2 + tid] * s;
    }
    if (tid < CO) {
        float s = bnf[tid] * rsqrtf(bnf[3 * CO + tid] + EPSV);
        sf[tid] = s; g_bf[tid] = bnf[CO + tid] - bnf[2 * CO + tid] * s;
    }
    __syncthreads();
    for (int i = tid; i < C2 * X_LD; i += blockDim.x) {
        int o = i / X_LD, k = i % X_LD;
        float q = 0.f, kk = 0.f, v = 0.f;
        if (k < CIN) {
            q = Wq[o * CIN + k] * sq[o];
            kk = Wk[o * CIN + k] * sk[o];
            v = Wv[o * CIN + k] * sv[o];
        } else if (k == CIN) {   // bias row
            q = shq[o]; kk = shk[o]; v = shv[o];
        }
        g_Wqh[i] = __float2half(q);
        g_Wkh[i] = __float2half(kk);
        g_Wvh[i] = __float2half(v);
    }
    for (int i = tid; i < CO * C2; i += blockDim.x) {
        int o = i >> 7;
        g_Wf[0][i] = Wf[i] * sf[o];
    }
}

// ---------------- pass 1: k,v GEMMs + kv accumulation (wmma) ----------------
__global__ void __launch_bounds__(256, 1) pass1_kernel(const float* __restrict__ x) {
    extern __shared__ char sm[];
    __half* xh = (__half*)(sm + P1_XH);    // [n][k] row-major A / col-major B view
    __half* wk = (__half*)(sm + P1_WK);    // [o][k]
    __half* wv = (__half*)(sm + P1_WV);
    __half* kf = (__half*)(sm + P1_KF);    // [c][n] ld H_LD
    __half* vf = (__half*)(sm + P1_VF);    // [d][n] ld H_LD
    float* scr = (float*)(sm + P1_SCR);    // [128][S_LD]

    const int tid = threadIdx.x, w = tid >> 5;
    const int b = blockIdx.x >> 4, split = blockIdx.x & 15;
    const float* xb = x + (size_t)b * CIN * NN;
    const int m0 = (w >> 1) * 32, n0 = (w & 1) * 64;

    for (int i = tid; i < C2 * X_LD; i += 256) { wk[i] = g_Wkh[i]; wv[i] = g_Wvh[i]; }
    // constant K rows of x: bias row = 1, pad rows = 0
    for (int n = tid; n < 128; n += 256) {
        xh[n * X_LD + CIN] = __float2half(1.0f);
        for (int k = CIN + 1; k < KP; ++k) xh[n * X_LD + k] = __float2half(0.0f);
    }

    wmma::fragment<wmma::accumulator, 16, 16, 16, float> kvacc[2][4];
#pragma unroll
    for (int mi = 0; mi < 2; ++mi)
#pragma unroll
        for (int ni = 0; ni < 4; ++ni) wmma::fill_fragment(kvacc[mi][ni], 0.0f);

    for (int t = 0; t < 8; ++t) {
        const int nbase = split * 1024 + t * 128;
        for (int i = tid; i < CIN * 128; i += 256) {
            int c = i >> 7, n = i & 127;
            xh[n * X_LD + c] = __float2half(__ldg(xb + (size_t)c * NN + nbase + n));
        }
        __syncthreads();

        // ---- k = Wk @ x : D[c][n], A=wk row-major, B=xh col-major ----
        {
            wmma::fragment<wmma::accumulator, 16, 16, 16, float> acc[2][4];
#pragma unroll
            for (int mi = 0; mi < 2; ++mi)
#pragma unroll
                for (int ni = 0; ni < 4; ++ni) wmma::fill_fragment(acc[mi][ni], 0.0f);
#pragma unroll
            for (int kk = 0; kk < KP / 16; ++kk) {
                wmma::fragment<wmma::matrix_a, 16, 16, 16, __half, wmma::row_major> af[2];
#pragma unroll
                for (int mi = 0; mi < 2; ++mi)
                    wmma::load_matrix_sync(af[mi], wk + (m0 + mi * 16) * X_LD + kk * 16, X_LD);
#pragma unroll
                for (int ni = 0; ni < 4; ++ni) {
                    wmma::fragment<wmma::matrix_b, 16, 16, 16, __half, wmma::col_major> bf;
                    wmma::load_matrix_sync(bf, xh + (n0 + ni * 16) * X_LD + kk * 16, X_LD);
#pragma unroll
                    for (int mi = 0; mi < 2; ++mi) wmma::mma_sync(acc[mi][ni], af[mi], bf, acc[mi][ni]);
                }
            }
#pragma unroll
            for (int mi = 0; mi < 2; ++mi)
#pragma unroll
                for (int ni = 0; ni < 4; ++ni)
                    wmma::store_matrix_sync(scr + (m0 + mi * 16) * S_LD + n0 + ni * 16, acc[mi][ni], S_LD, wmma::mem_row_major);
        }
        __syncthreads();
        for (int i = tid; i < C2 * 128; i += 256) {
            int c = i >> 7, n = i & 127;
            kf[c * H_LD + n] = __float2half(fmaxf(scr[c * S_LD + n], 0.f));
        }
        __syncthreads();

        // ---- v = Wv @ x ----
        {
            wmma::fragment<wmma::accumulator, 16, 16, 16, float> acc[2][4];
#pragma unroll
            for (int mi = 0; mi < 2; ++mi)
#pragma unroll
                for (int ni = 0; ni < 4; ++ni) wmma::fill_fragment(acc[mi][ni], 0.0f);
#pragma unroll
            for (int kk = 0; kk < KP / 16; ++kk) {
                wmma::fragment<wmma::matrix_a, 16, 16, 16, __half, wmma::row_major> af[2];
#pragma unroll
                for (int mi = 0; mi < 2; ++mi)
                    wmma::load_matrix_sync(af[mi], wv + (m0 + mi * 16) * X_LD + kk * 16, X_LD);
#pragma unroll
                for (int ni = 0; ni < 4; ++ni) {
                    wmma::fragment<wmma::matrix_b, 16, 16, 16, __half, wmma::col_major> bf;
                    wmma::load_matrix_sync(bf, xh + (n0 + ni * 16) * X_LD + kk * 16, X_LD);
#pragma unroll
                    for (int mi = 0; mi < 2; ++mi) wmma::mma_sync(acc[mi][ni], af[mi], bf, acc[mi][ni]);
                }
            }
#pragma unroll
            for (int mi = 0; mi < 2; ++mi)
#pragma unroll
                for (int ni = 0; ni < 4; ++ni)
                    wmma::store_matrix_sync(scr + (m0 + mi * 16) * S_LD + n0 + ni * 16, acc[mi][ni], S_LD, wmma::mem_row_major);
        }
        __syncthreads();
        for (int i = tid; i < C2 * 128; i += 256) {
            int d = i >> 7, n = i & 127;
            vf[d * H_LD + n] = __float2half(fmaxf(scr[d * S_LD + n], 0.f));
        }
        __syncthreads();

        // ---- kv[c][d] += k[c][:] . v[d][:] : A=kf row-major, B=vf col-major ----
#pragma unroll
        for (int kk = 0; kk < 8; ++kk) {
            wmma::fragment<wmma::matrix_a, 16, 16, 16, __half, wmma::row_major> af[2];
#pragma unroll
            for (int mi = 0; mi < 2; ++mi)
                wmma::load_matrix_sync(af[mi], kf + (m0 + mi * 16) * H_LD + kk * 16, H_LD);
#pragma unroll
            for (int ni = 0; ni < 4; ++ni) {
                wmma::fragment<wmma::matrix_b, 16, 16, 16, __half, wmma::col_major> bf;
                wmma::load_matrix_sync(bf, vf + (n0 + ni * 16) * H_LD + kk * 16, H_LD);
#pragma unroll
                for (int mi = 0; mi < 2; ++mi) wmma::mma_sync(kvacc[mi][ni], af[mi], bf, kvacc[mi][ni]);
            }
        }
        __syncthreads();
    }

    float* part = g_kvpart[blockIdx.x];
#pragma unroll
    for (int mi = 0; mi < 2; ++mi)
#pragma unroll
        for (int ni = 0; ni < 4; ++ni)
            wmma::store_matrix_sync(part + (m0 + mi * 16) * C2 + n0 + ni * 16, kvacc[mi][ni], C2, wmma::mem_row_major);
}

// ---------------- reduce kv partials + form M = (Wf . kv^T)/64 ----------------
__global__ void mkernel(void) {
    extern __shared__ float kvs[];   // [c][d]
    const int b = blockIdx.x, tid = threadIdx.x;
    for (int i = tid; i < C2 * C2; i += 256) {
        float s = 0.f;
#pragma unroll
        for (int p = 0; p < 16; ++p) s += g_kvpart[b * 16 + p][i];
        kvs[i] = s;
    }
    __syncthreads();
    for (int i = tid; i < CO * C2; i += 256) {
        int o = i >> 7, c = i & 127;
        float acc = 0.f;
#pragma unroll 8
        for (int d = 0; d < C2; ++d) acc = fmaf(g_Wf[o][d], kvs[c * C2 + d], acc);
        g_M[b][o][c] = acc * (1.f / 64.f);
    }
}

// ---------------- pass 2: q GEMM + out = relu(64*(q @ M^T) + bf) ----------------
__global__ void __launch_bounds__(256, 1) pass2_kernel(const float* __restrict__ x, float* __restrict__ out) {
    extern __shared__ char sm[];
    __half* xh = (__half*)(sm + P2_XH);
    __half* wq = (__half*)(sm + P2_WQ);
    __half* qh = (__half*)(sm + P2_QH);    // [n][c] ld H_LD
    __half* mh = (__half*)(sm + P2_MH);    // [o][c] ld H_LD
    float* scr = (float*)(sm + P2_SCR);

    const int tid = threadIdx.x, w = tid >> 5;
    const int b = blockIdx.x >> 5, split = blockIdx.x & 31;
    const float* xb = x + (size_t)b * CIN * NN;
    const int m0 = (w >> 1) * 32, n0 = (w & 1) * 64;   // q GEMM tiling
    const int o0 = (w & 1) * 32;                       // out GEMM tiling

    for (int i = tid; i < C2 * X_LD; i += 256) wq[i] = g_Wqh[i];
    for (int i = tid; i < CO * C2; i += 256) {
        int o = i >> 7, c = i & 127;
        mh[o * H_LD + c] = __float2half(g_M[b][o][c]);
    }
    for (int n = tid; n < 128; n += 256) {
        xh[n * X_LD + CIN] = __float2half(1.0f);
        for (int k = CIN + 1; k < KP; ++k) xh[n * X_LD + k] = __float2half(0.0f);
    }

    for (int t = 0; t < 4; ++t) {
        const int nbase = split * 512 + t * 128;
        for (int i = tid; i < CIN * 128; i += 256) {
            int c = i >> 7, n = i & 127;
            xh[n * X_LD + c] = __float2half(__ldg(xb + (size_t)c * NN + nbase + n));
        }
        __syncthreads();

        // ---- q : D[n][c], A=xh row-major [n][k], B=wq col-major (k,c)->wq[c][k] ----
        {
            wmma::fragment<wmma::accumulator, 16, 16, 16, float> acc[2][4];
#pragma unroll
            for (int mi = 0; mi < 2; ++mi)
#pragma unroll
                for (int ni = 0; ni < 4; ++ni) wmma::fill_fragment(acc[mi][ni], 0.0f);
#pragma unroll
            for (int kk = 0; kk < KP / 16; ++kk) {
                wmma::fragment<wmma::matrix_a, 16, 16, 16, __half, wmma::row_major> af[2];
#pragma unroll
                for (int mi = 0; mi < 2; ++mi)
                    wmma::load_matrix_sync(af[mi], xh + (m0 + mi * 16) * X_LD + kk * 16, X_LD);
#pragma unroll
                for (int ni = 0; ni < 4; ++ni) {
                    wmma::fragment<wmma::matrix_b, 16, 16, 16, __half, wmma::col_major> bf;
                    wmma::load_matrix_sync(bf, wq + (n0 + ni * 16) * X_LD + kk * 16, X_LD);
#pragma unroll
                    for (int mi = 0; mi < 2; ++mi) wmma::mma_sync(acc[mi][ni], af[mi], bf, acc[mi][ni]);
                }
            }
#pragma unroll
            for (int mi = 0; mi < 2; ++mi)
#pragma unroll
                for (int ni = 0; ni < 4; ++ni)
                    wmma::store_matrix_sync(scr + (m0 + mi * 16) * S_LD + n0 + ni * 16, acc[mi][ni], S_LD, wmma::mem_row_major);
        }
        __syncthreads();
        for (int i = tid; i < C2 * 128; i += 256) {
            int n = i >> 7, c = i & 127;
            qh[n * H_LD + c] = __float2half(fmaxf(scr[n * S_LD + c], 0.f));
        }
        __syncthreads();

        // ---- out : D[n][o], A=qh row-major, B=mh col-major (c,o)->mh[o][c] ----
        {
            wmma::fragment<wmma::accumulator, 16, 16, 16, float> acc[2][2];
#pragma unroll
            for (int mi = 0; mi < 2; ++mi)
#pragma unroll
                for (int ni = 0; ni < 2; ++ni) wmma::fill_fragment(acc[mi][ni], 0.0f);
#pragma unroll
            for (int kk = 0; kk < 8; ++kk) {
                wmma::fragment<wmma::matrix_a, 16, 16, 16, __half, wmma::row_major> af[2];
#pragma unroll
                for (int mi = 0; mi < 2; ++mi)
                    wmma::load_matrix_sync(af[mi], qh + (m0 + mi * 16) * H_LD + kk * 16, H_LD);
#pragma unroll
                for (int ni = 0; ni < 2; ++ni) {
                    wmma::fragment<wmma::matrix_b, 16, 16, 16, __half, wmma::col_major> bf;
                    wmma::load_matrix_sync(bf, mh + (o0 + ni * 16) * H_LD + kk * 16, H_LD);
#pragma unroll
                    for (int mi = 0; mi < 2; ++mi) wmma::mma_sync(acc[mi][ni], af[mi], bf, acc[mi][ni]);
                }
            }
            // store transposed: scr[o][n] (col-major store)
#pragma unroll
            for (int mi = 0; mi < 2; ++mi)
#pragma unroll
                for (int ni = 0; ni < 2; ++ni)
                    wmma::store_matrix_sync(scr + (o0 + ni * 16) * S_LD + m0 + mi * 16, acc[mi][ni], S_LD, wmma::mem_col_major);
        }
        __syncthreads();
        for (int i = tid; i < CO * 128; i += 256) {
            int o = i >> 7, n = i & 127;
            out[(size_t)(b * CO + o) * NN + nbase + n] =
                fmaxf(scr[o * S_LD + n] * 64.f + g_bf[o], 0.f);
        }
        __syncthreads();
    }
}

// ---------------- launch ----------------
extern "C" void kernel_launch(void* const* d_in, const int* in_sizes, int n_in,
                              void* d_out, int out_size) {
    const float* x   = (const float*)d_in[0];
    const float* Wq  = (const float*)d_in[1];
    const float* Wk  = (const float*)d_in[2];
    const float* Wv  = (const float*)d_in[3];
    const float* Wf  = (const float*)d_in[4];
    const float* bnq = (const float*)d_in[5];
    const float* bnk = (const float*)d_in[6];
    const float* bnv = (const float*)d_in[7];
    const float* bnf = (const float*)d_in[8];
    float* out = (float*)d_out;

    cudaFuncSetAttribute(pass1_kernel, cudaFuncAttributeMaxDynamicSharedMemorySize, P1_TOTAL);
    cudaFuncSetAttribute(pass2_kernel, cudaFuncAttributeMaxDynamicSharedMemorySize, P2_TOTAL);
    cudaFuncSetAttribute(mkernel,      cudaFuncAttributeMaxDynamicSharedMemorySize, C2 * C2 * (int)sizeof(float));

    prep_kernel<<<1, 256>>>(Wq, Wk, Wv, Wf, bnq, bnk, bnv, bnf);
    pass1_kernel<<<128, 256, P1_TOTAL>>>(x);
    mkernel<<<BB, 256, C2 * C2 * (int)sizeof(float)>>>();
    pass2_kernel<<<256, 256, P2_TOTAL>>>(x, out);
}

// round 8
// speedup vs baseline: 1.5933x; 1.0857x over previous
#include <cuda_runtime.h>
#include <cuda_fp16.h>
#include <mma.h>
#include <cstdint>

using namespace nvcuda;

#define BB 8
#define CIN 67
#define C2 128
#define CO 64
#define NN 16384
#define EPSV 1e-5f

#define KP 80        // padded K for x GEMMs (67 data + bias row + zeros)
#define X_LD 88      // xh / weight smem leading dim (halfs)
#define H_LD 136     // k/v/q/m f16 smem leading dim
#define S_LD 132     // f32 scratch leading dim (pass2 out only)

// pass1 smem byte offsets
#define P1_XH  0
#define P1_WK  22528
#define P1_WV  45056
#define P1_KF  67584
#define P1_VF  102400
#define P1_TOTAL 137216
// pass2 smem byte offsets
#define P2_XH  0
#define P2_WQ  22528
#define P2_QH  45056
#define P2_MH  79872
#define P2_SCR 97280
#define P2_TOTAL 131072

#define P1_GRID 256   // 8 b x 32 splits, 4 tiles each
#define P2_GRID 512   // 8 b x 64 splits, 2 tiles each

// ---------------- device scratch ----------------
__device__ __half g_Wqh[C2 * X_LD];   // folded, [o][k]: k<67 data, k==67 bias, else 0
__device__ __half g_Wkh[C2 * X_LD];
__device__ __half g_Wvh[C2 * X_LD];
__device__ float g_Wf[CO][C2];
__device__ float g_bf[CO];
__device__ float g_M[BB][CO][C2];            // (Wf . kv^T) / 64
__device__ float g_kvpart[P1_GRID][C2 * C2]; // per-CTA kv partials [c][d]

// convert f32 accumulator fragment -> relu -> half accumulator fragment
template <typename FragF, typename FragH>
__device__ __forceinline__ void relu_to_half(const FragF& f, FragH& h) {
#pragma unroll
    for (int i = 0; i < f.num_elements; ++i)
        h.x[i] = __float2half(fmaxf(f.x[i], 0.0f));
}

// ---------------- prep: fold BN into weights, pack f16, bias-row trick ----------------
__global__ void prep_kernel(const float* __restrict__ Wq, const float* __restrict__ Wk,
                            const float* __restrict__ Wv, const float* __restrict__ Wf,
                            const float* __restrict__ bnq, const float* __restrict__ bnk,
                            const float* __restrict__ bnv, const float* __restrict__ bnf) {
    __shared__ float sq[C2], sk[C2], sv[C2], shq[C2], shk[C2], shv[C2], sf[CO];
    int tid = threadIdx.x;
    if (tid < C2) {
        float s;
        s = bnq[tid] * rsqrtf(bnq[3 * C2 + tid] + EPSV); sq[tid] = s; shq[tid] = bnq[C2 + tid] - bnq[2 * C2 + tid] * s;
        s = bnk[tid] * rsqrtf(bnk[3 * C2 + tid] + EPSV); sk[tid] = s; shk[tid] = bnk[C2 + tid] - bnk[2 * C2 + tid] * s;
        s = bnv[tid] * rsqrtf(bnv[3 * C2 + tid] + EPSV); sv[tid] = s; shv[tid] = bnv[C2 + tid] - bnv[2 * C2 + tid] * s;
    }
    if (tid < CO) {
        float s = bnf[tid] * rsqrtf(bnf[3 * CO + tid] + EPSV);
        sf[tid] = s; g_bf[tid] = bnf[CO + tid] - bnf[2 * CO + tid] * s;
    }
    __syncthreads();
    for (int i = tid; i < C2 * X_LD; i += blockDim.x) {
        int o = i / X_LD, k = i % X_LD;
        float q = 0.f, kk = 0.f, v = 0.f;
        if (k < CIN) {
            q = Wq[o * CIN + k] * sq[o];
            kk = Wk[o * CIN + k] * sk[o];
            v = Wv[o * CIN + k] * sv[o];
        } else if (k == CIN) {
            q = shq[o]; kk = shk[o]; v = shv[o];
        }
        g_Wqh[i] = __float2half(q);
        g_Wkh[i] = __float2half(kk);
        g_Wvh[i] = __float2half(v);
    }
    for (int i = tid; i < CO * C2; i += blockDim.x) {
        int o = i >> 7;
        g_Wf[0][i] = Wf[i] * sf[o];
    }
}

// ---------------- pass 1: k,v GEMMs + kv accumulation (wmma, 16 warps) ----------------
__global__ void __launch_bounds__(512, 1) pass1_kernel(const float* __restrict__ x) {
    extern __shared__ char sm[];
    __half* xh = (__half*)(sm + P1_XH);    // [n][k] (A row-major / B col-major view)
    __half* wk = (__half*)(sm + P1_WK);    // [o][k]
    __half* wv = (__half*)(sm + P1_WV);
    __half* kf = (__half*)(sm + P1_KF);    // [c][n] ld H_LD
    __half* vf = (__half*)(sm + P1_VF);    // [d][n] ld H_LD

    const int tid = threadIdx.x, w = tid >> 5;
    const int b = blockIdx.x >> 5, split = blockIdx.x & 31;
    const float* xb = x + (size_t)b * CIN * NN;
    const int m0 = (w >> 2) * 32, n0 = (w & 3) * 32;

    for (int i = tid; i < C2 * X_LD; i += 512) { wk[i] = g_Wkh[i]; wv[i] = g_Wvh[i]; }
    for (int n = tid; n < 128; n += 512) {
        xh[n * X_LD + CIN] = __float2half(1.0f);
        for (int k = CIN + 1; k < KP; ++k) xh[n * X_LD + k] = __float2half(0.0f);
    }

    wmma::fragment<wmma::accumulator, 16, 16, 16, float> kvacc[2][2];
#pragma unroll
    for (int mi = 0; mi < 2; ++mi)
#pragma unroll
        for (int ni = 0; ni < 2; ++ni) wmma::fill_fragment(kvacc[mi][ni], 0.0f);

    for (int t = 0; t < 4; ++t) {
        const int nbase = split * 512 + t * 128;
        for (int i = tid; i < CIN * 128; i += 512) {
            int c = i >> 7, n = i & 127;
            xh[n * X_LD + c] = __float2half(__ldg(xb + (size_t)c * NN + nbase + n));
        }
        __syncthreads();

        // ---- k = Wk@x and v = Wv@x : D[c][n]; fragment-level relu->f16 store ----
        {
            wmma::fragment<wmma::accumulator, 16, 16, 16, float> acck[2][2], accv[2][2];
#pragma unroll
            for (int mi = 0; mi < 2; ++mi)
#pragma unroll
                for (int ni = 0; ni < 2; ++ni) { wmma::fill_fragment(acck[mi][ni], 0.0f); wmma::fill_fragment(accv[mi][ni], 0.0f); }
#pragma unroll
            for (int kk = 0; kk < KP / 16; ++kk) {
                wmma::fragment<wmma::matrix_a, 16, 16, 16, __half, wmma::row_major> afk[2], afv[2];
                wmma::fragment<wmma::matrix_b, 16, 16, 16, __half, wmma::col_major> bf[2];
#pragma unroll
                for (int mi = 0; mi < 2; ++mi) {
                    wmma::load_matrix_sync(afk[mi], wk + (m0 + mi * 16) * X_LD + kk * 16, X_LD);
                    wmma::load_matrix_sync(afv[mi], wv + (m0 + mi * 16) * X_LD + kk * 16, X_LD);
                }
#pragma unroll
                for (int ni = 0; ni < 2; ++ni)
                    wmma::load_matrix_sync(bf[ni], xh + (n0 + ni * 16) * X_LD + kk * 16, X_LD);
#pragma unroll
                for (int mi = 0; mi < 2; ++mi)
#pragma unroll
                    for (int ni = 0; ni < 2; ++ni) {
                        wmma::mma_sync(acck[mi][ni], afk[mi], bf[ni], acck[mi][ni]);
                        wmma::mma_sync(accv[mi][ni], afv[mi], bf[ni], accv[mi][ni]);
                    }
            }
            wmma::fragment<wmma::accumulator, 16, 16, 16, __half> h;
#pragma unroll
            for (int mi = 0; mi < 2; ++mi)
#pragma unroll
                for (int ni = 0; ni < 2; ++ni) {
                    relu_to_half(acck[mi][ni], h);
                    wmma::store_matrix_sync(kf + (m0 + mi * 16) * H_LD + n0 + ni * 16, h, H_LD, wmma::mem_row_major);
                    relu_to_half(accv[mi][ni], h);
                    wmma::store_matrix_sync(vf + (m0 + mi * 16) * H_LD + n0 + ni * 16, h, H_LD, wmma::mem_row_major);
                }
        }
        __syncthreads();

        // ---- kv[c][d] += k[c][:] . v[d][:] ----
#pragma unroll
        for (int kk = 0; kk < 8; ++kk) {
            wmma::fragment<wmma::matrix_a, 16, 16, 16, __half, wmma::row_major> af[2];
            wmma::fragment<wmma::matrix_b, 16, 16, 16, __half, wmma::col_major> bf[2];
#pragma unroll
            for (int mi = 0; mi < 2; ++mi)
                wmma::load_matrix_sync(af[mi], kf + (m0 + mi * 16) * H_LD + kk * 16, H_LD);
#pragma unroll
            for (int ni = 0; ni < 2; ++ni)
                wmma::load_matrix_sync(bf[ni], vf + (n0 + ni * 16) * H_LD + kk * 16, H_LD);
#pragma unroll
            for (int mi = 0; mi < 2; ++mi)
#pragma unroll
                for (int ni = 0; ni < 2; ++ni) wmma::mma_sync(kvacc[mi][ni], af[mi], bf[ni], kvacc[mi][ni]);
        }
        __syncthreads();
    }

    float* part = g_kvpart[blockIdx.x];
#pragma unroll
    for (int mi = 0; mi < 2; ++mi)
#pragma unroll
        for (int ni = 0; ni < 2; ++ni)
            wmma::store_matrix_sync(part + (m0 + mi * 16) * C2 + n0 + ni * 16, kvacc[mi][ni], C2, wmma::mem_row_major);
}

// ---------------- reduce kv partials + form M = (Wf . kv^T)/64 ----------------
__global__ void mkernel(void) {
    extern __shared__ float kvs[];   // [c][d]
    const int b = blockIdx.x, tid = threadIdx.x;
    for (int i = tid; i < C2 * C2; i += 256) {
        float s = 0.f;
#pragma unroll
        for (int p = 0; p < 32; ++p) s += g_kvpart[b * 32 + p][i];
        kvs[i] = s;
    }
    __syncthreads();
    for (int i = tid; i < CO * C2; i += 256) {
        int o = i >> 7, c = i & 127;
        float acc = 0.f;
#pragma unroll 8
        for (int d = 0; d < C2; ++d) acc = fmaf(g_Wf[o][d], kvs[c * C2 + d], acc);
        g_M[b][o][c] = acc * (1.f / 64.f);
    }
}

// ---------------- pass 2: q GEMM + out = relu(64*(q @ M^T) + bf) ----------------
__global__ void __launch_bounds__(512, 1) pass2_kernel(const float* __restrict__ x, float* __restrict__ out) {
    extern __shared__ char sm[];
    __half* xh = (__half*)(sm + P2_XH);
    __half* wq = (__half*)(sm + P2_WQ);
    __half* qh = (__half*)(sm + P2_QH);    // [n][c] ld H_LD
    __half* mh = (__half*)(sm + P2_MH);    // [o][c] ld H_LD
    float* scr = (float*)(sm + P2_SCR);    // [o][n] ld S_LD

    const int tid = threadIdx.x, w = tid >> 5;
    const int b = blockIdx.x >> 6, split = blockIdx.x & 63;
    const float* xb = x + (size_t)b * CIN * NN;
    const int m0 = (w >> 2) * 32, n0 = (w & 3) * 32;   // q GEMM tiling
    const int o0 = (w & 3) * 16;                       // out GEMM tiling

    for (int i = tid; i < C2 * X_LD; i += 512) wq[i] = g_Wqh[i];
    for (int i = tid; i < CO * C2; i += 512) {
        int o = i >> 7, c = i & 127;
        mh[o * H_LD + c] = __float2half(g_M[b][o][c]);
    }
    for (int n = tid; n < 128; n += 512) {
        xh[n * X_LD + CIN] = __float2half(1.0f);
        for (int k = CIN + 1; k < KP; ++k) xh[n * X_LD + k] = __float2half(0.0f);
    }

    for (int t = 0; t < 2; ++t) {
        const int nbase = split * 256 + t * 128;
        for (int i = tid; i < CIN * 128; i += 512) {
            int c = i >> 7, n = i & 127;
            xh[n * X_LD + c] = __float2half(__ldg(xb + (size_t)c * NN + nbase + n));
        }
        __syncthreads();

        // ---- q : D[n][c], A=xh row-major, B=wq col-major; fragment relu->f16 ----
        {
            wmma::fragment<wmma::accumulator, 16, 16, 16, float> acc[2][2];
#pragma unroll
            for (int mi = 0; mi < 2; ++mi)
#pragma unroll
                for (int ni = 0; ni < 2; ++ni) wmma::fill_fragment(acc[mi][ni], 0.0f);
#pragma unroll
            for (int kk = 0; kk < KP / 16; ++kk) {
                wmma::fragment<wmma::matrix_a, 16, 16, 16, __half, wmma::row_major> af[2];
                wmma::fragment<wmma::matrix_b, 16, 16, 16, __half, wmma::col_major> bf[2];
#pragma unroll
                for (int mi = 0; mi < 2; ++mi)
                    wmma::load_matrix_sync(af[mi], xh + (m0 + mi * 16) * X_LD + kk * 16, X_LD);
#pragma unroll
                for (int ni = 0; ni < 2; ++ni)
                    wmma::load_matrix_sync(bf[ni], wq + (n0 + ni * 16) * X_LD + kk * 16, X_LD);
#pragma unroll
                for (int mi = 0; mi < 2; ++mi)
#pragma unroll
                    for (int ni = 0; ni < 2; ++ni) wmma::mma_sync(acc[mi][ni], af[mi], bf[ni], acc[mi][ni]);
            }
            wmma::fragment<wmma::accumulator, 16, 16, 16, __half> h;
#pragma unroll
            for (int mi = 0; mi < 2; ++mi)
#pragma unroll
                for (int ni = 0; ni < 2; ++ni) {
                    relu_to_half(acc[mi][ni], h);
                    wmma::store_matrix_sync(qh + (m0 + mi * 16) * H_LD + n0 + ni * 16, h, H_LD, wmma::mem_row_major);
                }
        }
        __syncthreads();

        // ---- out : D[n][o], A=qh row-major, B=mh col-major; store transposed f32 ----
        {
            wmma::fragment<wmma::accumulator, 16, 16, 16, float> acc[2];
#pragma unroll
            for (int mi = 0; mi < 2; ++mi) wmma::fill_fragment(acc[mi], 0.0f);
#pragma unroll
            for (int kk = 0; kk < 8; ++kk) {
                wmma::fragment<wmma::matrix_a, 16, 16, 16, __half, wmma::row_major> af[2];
                wmma::fragment<wmma::matrix_b, 16, 16, 16, __half, wmma::col_major> bf;
#pragma unroll
                for (int mi = 0; mi < 2; ++mi)
                    wmma::load_matrix_sync(af[mi], qh + (m0 + mi * 16) * H_LD + kk * 16, H_LD);
                wmma::load_matrix_sync(bf, mh + o0 * H_LD + kk * 16, H_LD);
#pragma unroll
                for (int mi = 0; mi < 2; ++mi) wmma::mma_sync(acc[mi], af[mi], bf, acc[mi]);
            }
#pragma unroll
            for (int mi = 0; mi < 2; ++mi)
                wmma::store_matrix_sync(scr + o0 * S_LD + m0 + mi * 16, acc[mi], S_LD, wmma::mem_col_major);
        }
        __syncthreads();

        for (int i = tid; i < CO * 128; i += 512) {
            int o = i >> 7, n = i & 127;
            out[(size_t)(b * CO + o) * NN + nbase + n] =
                fmaxf(scr[o * S_LD + n] * 64.f + g_bf[o], 0.f);
        }
        __syncthreads();
    }
}

// ---------------- launch ----------------
extern "C" void kernel_launch(void* const* d_in, const int* in_sizes, int n_in,
                              void* d_out, int out_size) {
    const float* x   = (const float*)d_in[0];
    const float* Wq  = (const float*)d_in[1];
    const float* Wk  = (const float*)d_in[2];
    const float* Wv  = (const float*)d_in[3];
    const float* Wf  = (const float*)d_in[4];
    const float* bnq = (const float*)d_in[5];
    const float* bnk = (const float*)d_in[6];
    const float* bnv = (const float*)d_in[7];
    const float* bnf = (const float*)d_in[8];
    float* out = (float*)d_out;

    cudaFuncSetAttribute(pass1_kernel, cudaFuncAttributeMaxDynamicSharedMemorySize, P1_TOTAL);
    cudaFuncSetAttribute(pass2_kernel, cudaFuncAttributeMaxDynamicSharedMemorySize, P2_TOTAL);
    cudaFuncSetAttribute(mkernel,      cudaFuncAttributeMaxDynamicSharedMemorySize, C2 * C2 * (int)sizeof(float));

    prep_kernel<<<1, 256>>>(Wq, Wk, Wv, Wf, bnq, bnk, bnv, bnf);
    pass1_kernel<<<P1_GRID, 512, P1_TOTAL>>>(x);
    mkernel<<<BB, 256, C2 * C2 * (int)sizeof(float)>>>();
    pass2_kernel<<<P2_GRID, 512, P2_TOTAL>>>(x, out);
}

// round 9
// speedup vs baseline: 4.1427x; 2.6000x over previous
#include <cuda_runtime.h>
#include <cuda_fp16.h>
#include <mma.h>
#include <cstdint>

using namespace nvcuda;

#define BB 8
#define CIN 67
#define C2 128
#define CO 64
#define NN 16384
#define EPSV 1e-5f

#define KP 80        // padded K for x GEMMs (67 data + bias row + zeros)
#define X_LD 88      // xh leading dim (halfs)
#define KV_LD 264    // kf/vf leading dim (256 n + 8)
#define Q_LD 136     // qh / mh leading dim (128 c + 8)
#define SC_LD 260    // f32 out scratch leading dim (256 n + 4)
#define TNS 256      // n super-tile

// pass1 smem byte offsets
#define P1_XH 0          // 256*88*2   = 45056
#define P1_WK 45056      // 128*88*2   = 22528
#define P1_WV 67584      // 22528
#define P1_KF 90112      // 128*264*2  = 67584
#define P1_VF 157696     // 67584
#define P1_TOTAL 225280
// pass2 smem byte offsets
#define P2_XH 0          // 45056
#define P2_WQ 45056      // 22528
#define P2_QH 67584      // 256*136*2  = 69632
#define P2_MH 137216     // 64*136*2   = 17408
#define P2_SCR 154624    // 64*260*4   = 66560
#define P2_TOTAL 221184

#define P1_GRID 128   // 8 b x 16 splits, 4 super-tiles each
#define P2_GRID 128

// ---------------- device scratch ----------------
__device__ __align__(16) __half g_Wqh[C2 * X_LD];   // folded [o][k]: k<67 data, k==67 bias, else 0
__device__ __align__(16) __half g_Wkh[C2 * X_LD];
__device__ __align__(16) __half g_Wvh[C2 * X_LD];
__device__ float g_Wf[CO][C2];
__device__ float g_bf[CO];
__device__ float g_M[BB][CO][C2];            // (Wf . kv^T) / 64
__device__ float g_kvpart[P1_GRID][C2 * C2]; // per-CTA kv partials [c][d]

// convert f32 accumulator fragment -> relu -> half accumulator fragment
template <typename FragF, typename FragH>
__device__ __forceinline__ void relu_to_half(const FragF& f, FragH& h) {
#pragma unroll
    for (int i = 0; i < f.num_elements; ++i)
        h.x[i] = __float2half(fmaxf(f.x[i], 0.0f));
}

// ---------------- prep: fold BN into weights, pack f16, bias-row trick ----------------
__global__ void prep_kernel(const float* __restrict__ Wq, const float* __restrict__ Wk,
                            const float* __restrict__ Wv, const float* __restrict__ Wf,
                            const float* __restrict__ bnq, const float* __restrict__ bnk,
                            const float* __restrict__ bnv, const float* __restrict__ bnf) {
    __shared__ float sq[C2], sk[C2], sv[C2], shq[C2], shk[C2], shv[C2], sf[CO];
    int tid = threadIdx.x;
    if (tid < C2) {
        float s;
        s = bnq[tid] * rsqrtf(bnq[3 * C2 + tid] + EPSV); sq[tid] = s; shq[tid] = bnq[C2 + tid] - bnq[2 * C2 + tid] * s;
        s = bnk[tid] * rsqrtf(bnk[3 * C2 + tid] + EPSV); sk[tid] = s; shk[tid] = bnk[C2 + tid] - bnk[2 * C2 + tid] * s;
        s = bnv[tid] * rsqrtf(bnv[3 * C2 + tid] + EPSV); sv[tid] = s; shv[tid] = bnv[C2 + tid] - bnv[2 * C2 + tid] * s;
    }
    if (tid < CO) {
        float s = bnf[tid] * rsqrtf(bnf[3 * CO + tid] + EPSV);
        sf[tid] = s; g_bf[tid] = bnf[CO + tid] - bnf[2 * CO + tid] * s;
    }
    __syncthreads();
    for (int i = tid; i < C2 * X_LD; i += blockDim.x) {
        int o = i / X_LD, k = i % X_LD;
        float q = 0.f, kk = 0.f, v = 0.f;
        if (k < CIN) {
            q = Wq[o * CIN + k] * sq[o];
            kk = Wk[o * CIN + k] * sk[o];
            v = Wv[o * CIN + k] * sv[o];
        } else if (k == CIN) {
            q = shq[o]; kk = shk[o]; v = shv[o];
        }
        g_Wqh[i] = __float2half(q);
        g_Wkh[i] = __float2half(kk);
        g_Wvh[i] = __float2half(v);
    }
    for (int i = tid; i < CO * C2; i += blockDim.x) {
        int o = i >> 7;
        g_Wf[0][i] = Wf[i] * sf[o];
    }
}

// ---------------- pass 1: k,v GEMMs + kv accumulation (wmma, 256-wide tiles) ----------------
__global__ void __launch_bounds__(512, 1) pass1_kernel(const float* __restrict__ x) {
    extern __shared__ char sm[];
    __half* xh = (__half*)(sm + P1_XH);    // [n(256)][k] row-major / col-major B view
    __half* wk = (__half*)(sm + P1_WK);    // [o][k]
    __half* wv = (__half*)(sm + P1_WV);
    __half* kf = (__half*)(sm + P1_KF);    // [c][n(256)] ld KV_LD
    __half* vf = (__half*)(sm + P1_VF);    // [d][n(256)] ld KV_LD

    const int tid = threadIdx.x, w = tid >> 5;
    const int b = blockIdx.x >> 4, split = blockIdx.x & 15;
    const float* xb = x + (size_t)b * CIN * NN;
    const int m0 = (w >> 2) * 32, nw = (w & 3) * 32;

    for (int i = tid; i < C2 * X_LD; i += 512) { wk[i] = g_Wkh[i]; wv[i] = g_Wvh[i]; }
    for (int n = tid; n < TNS; n += 512) {
        xh[n * X_LD + CIN] = __float2half(1.0f);
        for (int k = CIN + 1; k < KP; ++k) xh[n * X_LD + k] = __float2half(0.0f);
    }

    wmma::fragment<wmma::accumulator, 16, 16, 16, float> kvacc[2][2];
#pragma unroll
    for (int mi = 0; mi < 2; ++mi)
#pragma unroll
        for (int ni = 0; ni < 2; ++ni) wmma::fill_fragment(kvacc[mi][ni], 0.0f);

    for (int t = 0; t < 4; ++t) {
        const int nbase = split * 1024 + t * TNS;
        for (int i = tid; i < CIN * TNS; i += 512) {
            int c = i >> 8, n = i & 255;
            xh[n * X_LD + c] = __float2half(__ldg(xb + (size_t)c * NN + nbase + n));
        }
        __syncthreads();

        // ---- k = Wk@x, then v = Wv@x (sequential, reuse acc regs) ----
#pragma unroll
        for (int which = 0; which < 2; ++which) {
            const __half* wsrc = which ? wv : wk;
            __half* dst = which ? vf : kf;
#pragma unroll
            for (int hn = 0; hn < 2; ++hn) {
                const int n0 = hn * 128 + nw;
                wmma::fragment<wmma::accumulator, 16, 16, 16, float> acc[2][2];
#pragma unroll
                for (int mi = 0; mi < 2; ++mi)
#pragma unroll
                    for (int ni = 0; ni < 2; ++ni) wmma::fill_fragment(acc[mi][ni], 0.0f);
#pragma unroll
                for (int kk = 0; kk < KP / 16; ++kk) {
                    wmma::fragment<wmma::matrix_a, 16, 16, 16, __half, wmma::row_major> af[2];
                    wmma::fragment<wmma::matrix_b, 16, 16, 16, __half, wmma::col_major> bf[2];
#pragma unroll
                    for (int mi = 0; mi < 2; ++mi)
                        wmma::load_matrix_sync(af[mi], wsrc + (m0 + mi * 16) * X_LD + kk * 16, X_LD);
#pragma unroll
                    for (int ni = 0; ni < 2; ++ni)
                        wmma::load_matrix_sync(bf[ni], xh + (n0 + ni * 16) * X_LD + kk * 16, X_LD);
#pragma unroll
                    for (int mi = 0; mi < 2; ++mi)
#pragma unroll
                        for (int ni = 0; ni < 2; ++ni) wmma::mma_sync(acc[mi][ni], af[mi], bf[ni], acc[mi][ni]);
                }
                wmma::fragment<wmma::accumulator, 16, 16, 16, __half> h;
#pragma unroll
                for (int mi = 0; mi < 2; ++mi)
#pragma unroll
                    for (int ni = 0; ni < 2; ++ni) {
                        relu_to_half(acc[mi][ni], h);
                        wmma::store_matrix_sync(dst + (m0 + mi * 16) * KV_LD + n0 + ni * 16, h, KV_LD, wmma::mem_row_major);
                    }
            }
        }
        __syncthreads();

        // ---- kv[c][d] += k[c][:256] . v[d][:256] ----
#pragma unroll
        for (int kk = 0; kk < TNS / 16; ++kk) {
            wmma::fragment<wmma::matrix_a, 16, 16, 16, __half, wmma::row_major> af[2];
            wmma::fragment<wmma::matrix_b, 16, 16, 16, __half, wmma::col_major> bf[2];
#pragma unroll
            for (int mi = 0; mi < 2; ++mi)
                wmma::load_matrix_sync(af[mi], kf + (m0 + mi * 16) * KV_LD + kk * 16, KV_LD);
#pragma unroll
            for (int ni = 0; ni < 2; ++ni)
                wmma::load_matrix_sync(bf[ni], vf + (nw + ni * 16) * KV_LD + kk * 16, KV_LD);
#pragma unroll
            for (int mi = 0; mi < 2; ++mi)
#pragma unroll
                for (int ni = 0; ni < 2; ++ni) wmma::mma_sync(kvacc[mi][ni], af[mi], bf[ni], kvacc[mi][ni]);
        }
        __syncthreads();
    }

    float* part = g_kvpart[blockIdx.x];
#pragma unroll
    for (int mi = 0; mi < 2; ++mi)
#pragma unroll
        for (int ni = 0; ni < 2; ++ni)
            wmma::store_matrix_sync(part + (m0 + mi * 16) * C2 + nw + ni * 16, kvacc[mi][ni], C2, wmma::mem_row_major);
}

// ---------------- reduce kv partials + form M = (Wf . kv^T)/64 (64 blocks) ----------------
__global__ void mkernel(void) {
    __shared__ float kvs[16 * C2];   // slice of kv: [c_local][d]
    const int b = blockIdx.x >> 3, slice = blockIdx.x & 7;
    const int tid = threadIdx.x;
    for (int i = tid; i < 16 * C2; i += 256) {
        int cl = i >> 7, d = i & 127;
        int c = slice * 16 + cl;
        float s = 0.f;
#pragma unroll
        for (int p = 0; p < 16; ++p) s += g_kvpart[b * 16 + p][c * C2 + d];
        kvs[i] = s;
    }
    __syncthreads();
    for (int i = tid; i < CO * 16; i += 256) {
        int o = i >> 4, cl = i & 15;
        float acc = 0.f;
#pragma unroll 8
        for (int d = 0; d < C2; ++d) acc = fmaf(g_Wf[o][d], kvs[cl * C2 + d], acc);
        g_M[b][o][slice * 16 + cl] = acc * (1.f / 64.f);
    }
}

// ---------------- pass 2: q GEMM + out = relu(64*(q @ M^T) + bf) ----------------
__global__ void __launch_bounds__(512, 1) pass2_kernel(const float* __restrict__ x, float* __restrict__ out) {
    extern __shared__ char sm[];
    __half* xh = (__half*)(sm + P2_XH);    // [n(256)][k]
    __half* wq = (__half*)(sm + P2_WQ);    // [c][k]
    __half* qh = (__half*)(sm + P2_QH);    // [n(256)][c] ld Q_LD
    __half* mh = (__half*)(sm + P2_MH);    // [o][c] ld Q_LD
    float* scr = (float*)(sm + P2_SCR);    // [o][n(256)] ld SC_LD

    const int tid = threadIdx.x, w = tid >> 5;
    const int b = blockIdx.x >> 4, split = blockIdx.x & 15;
    const float* xb = x + (size_t)b * CIN * NN;
    const int mw = (w >> 2) * 32, nw = (w & 3) * 32;   // q GEMM warp tile
    const int o0 = (w & 3) * 16;                       // out GEMM warp tile

    for (int i = tid; i < C2 * X_LD; i += 512) wq[i] = g_Wqh[i];
    for (int i = tid; i < CO * C2; i += 512) {
        int o = i >> 7, c = i & 127;
        mh[o * Q_LD + c] = __float2half(g_M[b][o][c]);
    }
    for (int n = tid; n < TNS; n += 512) {
        xh[n * X_LD + CIN] = __float2half(1.0f);
        for (int k = CIN + 1; k < KP; ++k) xh[n * X_LD + k] = __float2half(0.0f);
    }

    for (int t = 0; t < 4; ++t) {
        const int nbase = split * 1024 + t * TNS;
        for (int i = tid; i < CIN * TNS; i += 512) {
            int c = i >> 8, n = i & 255;
            xh[n * X_LD + c] = __float2half(__ldg(xb + (size_t)c * NN + nbase + n));
        }
        __syncthreads();

        // ---- q : D[n][c], two n-halves ----
#pragma unroll
        for (int hn = 0; hn < 2; ++hn) {
            const int m0 = hn * 128 + mw;
            wmma::fragment<wmma::accumulator, 16, 16, 16, float> acc[2][2];
#pragma unroll
            for (int mi = 0; mi < 2; ++mi)
#pragma unroll
                for (int ni = 0; ni < 2; ++ni) wmma::fill_fragment(acc[mi][ni], 0.0f);
#pragma unroll
            for (int kk = 0; kk < KP / 16; ++kk) {
                wmma::fragment<wmma::matrix_a, 16, 16, 16, __half, wmma::row_major> af[2];
                wmma::fragment<wmma::matrix_b, 16, 16, 16, __half, wmma::col_major> bf[2];
#pragma unroll
                for (int mi = 0; mi < 2; ++mi)
                    wmma::load_matrix_sync(af[mi], xh + (m0 + mi * 16) * X_LD + kk * 16, X_LD);
#pragma unroll
                for (int ni = 0; ni < 2; ++ni)
                    wmma::load_matrix_sync(bf[ni], wq + (nw + ni * 16) * X_LD + kk * 16, X_LD);
#pragma unroll
                for (int mi = 0; mi < 2; ++mi)
#pragma unroll
                    for (int ni = 0; ni < 2; ++ni) wmma::mma_sync(acc[mi][ni], af[mi], bf[ni], acc[mi][ni]);
            }
            wmma::fragment<wmma::accumulator, 16, 16, 16, __half> h;
#pragma unroll
            for (int mi = 0; mi < 2; ++mi)
#pragma unroll
                for (int ni = 0; ni < 2; ++ni) {
                    relu_to_half(acc[mi][ni], h);
                    wmma::store_matrix_sync(qh + (m0 + mi * 16) * Q_LD + nw + ni * 16, h, Q_LD, wmma::mem_row_major);
                }
        }
        __syncthreads();

        // ---- out : D[n][o], two n-halves; store transposed f32 scr[o][n] ----
#pragma unroll
        for (int hn = 0; hn < 2; ++hn) {
            const int m0 = hn * 128 + mw;
            wmma::fragment<wmma::accumulator, 16, 16, 16, float> acc[2];
#pragma unroll
            for (int mi = 0; mi < 2; ++mi) wmma::fill_fragment(acc[mi], 0.0f);
#pragma unroll
            for (int kk = 0; kk < 8; ++kk) {
                wmma::fragment<wmma::matrix_a, 16, 16, 16, __half, wmma::row_major> af[2];
                wmma::fragment<wmma::matrix_b, 16, 16, 16, __half, wmma::col_major> bf;
#pragma unroll
                for (int mi = 0; mi < 2; ++mi)
                    wmma::load_matrix_sync(af[mi], qh + (m0 + mi * 16) * Q_LD + kk * 16, Q_LD);
                wmma::load_matrix_sync(bf, mh + o0 * Q_LD + kk * 16, Q_LD);
#pragma unroll
                for (int mi = 0; mi < 2; ++mi) wmma::mma_sync(acc[mi], af[mi], bf, acc[mi]);
            }
#pragma unroll
            for (int mi = 0; mi < 2; ++mi)
                wmma::store_matrix_sync(scr + o0 * SC_LD + m0 + mi * 16, acc[mi], SC_LD, wmma::mem_col_major);
        }
        __syncthreads();

        for (int i = tid; i < CO * TNS; i += 512) {
            int o = i >> 8, n = i & 255;
            out[(size_t)(b * CO + o) * NN + nbase + n] =
                fmaxf(scr[o * SC_LD + n] * 64.f + g_bf[o], 0.f);
        }
        __syncthreads();
    }
}

// ---------------- launch ----------------
extern "C" void kernel_launch(void* const* d_in, const int* in_sizes, int n_in,
                              void* d_out, int out_size) {
    const float* x   = (const float*)d_in[0];
    const float* Wq  = (const float*)d_in[1];
    const float* Wk  = (const float*)d_in[2];
    const float* Wv  = (const float*)d_in[3];
    const float* Wf  = (const float*)d_in[4];
    const float* bnq = (const float*)d_in[5];
    const float* bnk = (const float*)d_in[6];
    const float* bnv = (const float*)d_in[7];
    const float* bnf = (const float*)d_in[8];
    float* out = (float*)d_out;

    cudaFuncSetAttribute(pass1_kernel, cudaFuncAttributeMaxDynamicSharedMemorySize, P1_TOTAL);
    cudaFuncSetAttribute(pass2_kernel, cudaFuncAttributeMaxDynamicSharedMemorySize, P2_TOTAL);

    prep_kernel<<<1, 256>>>(Wq, Wk, Wv, Wf, bnq, bnk, bnv, bnf);
    pass1_kernel<<<P1_GRID, 512, P1_TOTAL>>>(x);
    mkernel<<<64, 256>>>();
    pass2_kernel<<<P2_GRID, 512, P2_TOTAL>>>(x, out);
}

// round 10
// speedup vs baseline: 4.7574x; 1.1484x over previous
#include <cuda_runtime.h>
#include <cuda_fp16.h>
#include <mma.h>
#include <cstdint>

using namespace nvcuda;

#define BB 8
#define CIN 67
#define C2 128
#define CO 64
#define NN 16384
#define EPSV 1e-5f

#define KP 80        // padded K (67 data + bias row 67 + zeros to 80)
#define X_LD 88      // weight smem leading dim (halfs), [o][k]
#define XN_LD 264    // xkn leading dim (256 n + 8), [k][n]
#define KV_LD 264    // kf/vf leading dim
#define Q_LD 136     // qh / mh leading dim (128 c + 8)
#define SC_LD 260    // f32 out scratch leading dim
#define TNS 256      // n super-tile

// pass1 smem byte offsets
#define P1_XK 0          // 80*264*2  = 42240
#define P1_WK 42240      // 128*88*2  = 22528
#define P1_WV 64768      // 22528
#define P1_KF 87296      // 128*264*2 = 67584
#define P1_VF 154880     // 67584
#define P1_TOTAL 222464
// pass2 smem byte offsets
#define P2_XK 0          // 42240
#define P2_WQ 42240      // 22528
#define P2_QH 64768      // 256*136*2 = 69632
#define P2_MH 134400     // 64*136*2  = 17408
#define P2_SCR 151808    // 64*260*4  = 66560
#define P2_TOTAL 218368

#define P1_GRID 128   // 8 b x 16 splits, 4 super-tiles each
#define P2_GRID 128

// ---------------- device scratch ----------------
__device__ __align__(16) __half g_Wqh[C2 * X_LD];
__device__ __align__(16) __half g_Wkh[C2 * X_LD];
__device__ __align__(16) __half g_Wvh[C2 * X_LD];
__device__ float g_Wf[CO][C2];
__device__ float g_bf[CO];
__device__ float g_M[BB][CO][C2];            // (Wf . kv^T) / 64
__device__ float g_kvpart[P1_GRID][C2 * C2];

template <typename FragF, typename FragH>
__device__ __forceinline__ void relu_to_half(const FragF& f, FragH& h) {
#pragma unroll
    for (int i = 0; i < f.num_elements; ++i)
        h.x[i] = __float2half(fmaxf(f.x[i], 0.0f));
}

// load x super-tile (float4 gmem reads) into xkn[k][n] f16, contiguous smem writes
__device__ __forceinline__ void load_x_tile(const float* __restrict__ xb, int nbase,
                                            __half* __restrict__ xkn, int tid) {
    const int total = CIN * (TNS / 4);   // 4288 float4 ops
    for (int i = tid; i < total; i += 512) {
        int c = i >> 6, n4 = (i & 63) << 2;
        const float4 v = *reinterpret_cast<const float4*>(xb + (size_t)c * NN + nbase + n4);
        __half2 lo = __floats2half2_rn(v.x, v.y);
        __half2 hi = __floats2half2_rn(v.z, v.w);
        *reinterpret_cast<__half2*>(xkn + c * XN_LD + n4)     = lo;
        *reinterpret_cast<__half2*>(xkn + c * XN_LD + n4 + 2) = hi;
    }
}

// ---------------- prep ----------------
__global__ void prep_kernel(const float* __restrict__ Wq, const float* __restrict__ Wk,
                            const float* __restrict__ Wv, const float* __restrict__ Wf,
                            const float* __restrict__ bnq, const float* __restrict__ bnk,
                            const float* __restrict__ bnv, const float* __restrict__ bnf) {
    __shared__ float sq[C2], sk[C2], sv[C2], shq[C2], shk[C2], shv[C2], sf[CO];
    int tid = threadIdx.x;
    if (tid < C2) {
        float s;
        s = bnq[tid] * rsqrtf(bnq[3 * C2 + tid] + EPSV); sq[tid] = s; shq[tid] = bnq[C2 + tid] - bnq[2 * C2 + tid] * s;
        s = bnk[tid] * rsqrtf(bnk[3 * C2 + tid] + EPSV); sk[tid] = s; shk[tid] = bnk[C2 + tid] - bnk[2 * C2 + tid] * s;
        s = bnv[tid] * rsqrtf(bnv[3 * C2 + tid] + EPSV); sv[tid] = s; shv[tid] = bnv[C2 + tid] - bnv[2 * C2 + tid] * s;
    }
    if (tid < CO) {
        float s = bnf[tid] * rsqrtf(bnf[3 * CO + tid] + EPSV);
        sf[tid] = s; g_bf[tid] = bnf[CO + tid] - bnf[2 * CO + tid] * s;
    }
    __syncthreads();
    for (int i = tid; i < C2 * X_LD; i += blockDim.x) {
        int o = i / X_LD, k = i % X_LD;
        float q = 0.f, kk = 0.f, v = 0.f;
        if (k < CIN) {
            q = Wq[o * CIN + k] * sq[o];
            kk = Wk[o * CIN + k] * sk[o];
            v = Wv[o * CIN + k] * sv[o];
        } else if (k == CIN) {
            q = shq[o]; kk = shk[o]; v = shv[o];
        }
        g_Wqh[i] = __float2half(q);
        g_Wkh[i] = __float2half(kk);
        g_Wvh[i] = __float2half(v);
    }
    for (int i = tid; i < CO * C2; i += blockDim.x) {
        int o = i >> 7;
        g_Wf[0][i] = Wf[i] * sf[o];
    }
}

// ---------------- pass 1 ----------------
__global__ void __launch_bounds__(512, 1) pass1_kernel(const float* __restrict__ x) {
    extern __shared__ char sm[];
    __half* xkn = (__half*)(sm + P1_XK);   // [k(80)][n(256)]
    __half* wk = (__half*)(sm + P1_WK);    // [o][k]
    __half* wv = (__half*)(sm + P1_WV);
    __half* kf = (__half*)(sm + P1_KF);    // [c][n] ld KV_LD
    __half* vf = (__half*)(sm + P1_VF);    // [d][n] ld KV_LD

    const int tid = threadIdx.x, w = tid >> 5;
    const int b = blockIdx.x >> 4, split = blockIdx.x & 15;
    const float* xb = x + (size_t)b * CIN * NN;
    const int m0 = (w >> 2) * 32, nw = (w & 3) * 32;

    for (int i = tid * 4; i < C2 * X_LD; i += 512 * 4) {
        *reinterpret_cast<uint2*>(wk + i) = *reinterpret_cast<const uint2*>(g_Wkh + i);
        *reinterpret_cast<uint2*>(wv + i) = *reinterpret_cast<const uint2*>(g_Wvh + i);
    }
    // bias row (k=67) = 1, pad rows 68..79 = 0
    for (int n = tid; n < TNS; n += 512) {
        xkn[CIN * XN_LD + n] = __float2half(1.0f);
#pragma unroll
        for (int k = CIN + 1; k < KP; ++k) xkn[k * XN_LD + n] = __float2half(0.0f);
    }

    wmma::fragment<wmma::accumulator, 16, 16, 16, float> kvacc[2][2];
#pragma unroll
    for (int mi = 0; mi < 2; ++mi)
#pragma unroll
        for (int ni = 0; ni < 2; ++ni) wmma::fill_fragment(kvacc[mi][ni], 0.0f);

    for (int t = 0; t < 4; ++t) {
        const int nbase = split * 1024 + t * TNS;
        load_x_tile(xb, nbase, xkn, tid);
        __syncthreads();

        // ---- k = Wk@x, then v = Wv@x : D[c][n]; A=w row-major, B=xkn row-major [k][n] ----
#pragma unroll
        for (int which = 0; which < 2; ++which) {
            const __half* wsrc = which ? wv : wk;
            __half* dst = which ? vf : kf;
#pragma unroll
            for (int hn = 0; hn < 2; ++hn) {
                const int n0 = hn * 128 + nw;
                wmma::fragment<wmma::accumulator, 16, 16, 16, float> acc[2][2];
#pragma unroll
                for (int mi = 0; mi < 2; ++mi)
#pragma unroll
                    for (int ni = 0; ni < 2; ++ni) wmma::fill_fragment(acc[mi][ni], 0.0f);
#pragma unroll
                for (int kk = 0; kk < KP / 16; ++kk) {
                    wmma::fragment<wmma::matrix_a, 16, 16, 16, __half, wmma::row_major> af[2];
                    wmma::fragment<wmma::matrix_b, 16, 16, 16, __half, wmma::row_major> bf[2];
#pragma unroll
                    for (int mi = 0; mi < 2; ++mi)
                        wmma::load_matrix_sync(af[mi], wsrc + (m0 + mi * 16) * X_LD + kk * 16, X_LD);
#pragma unroll
                    for (int ni = 0; ni < 2; ++ni)
                        wmma::load_matrix_sync(bf[ni], xkn + kk * 16 * XN_LD + n0 + ni * 16, XN_LD);
#pragma unroll
                    for (int mi = 0; mi < 2; ++mi)
#pragma unroll
                        for (int ni = 0; ni < 2; ++ni) wmma::mma_sync(acc[mi][ni], af[mi], bf[ni], acc[mi][ni]);
                }
                wmma::fragment<wmma::accumulator, 16, 16, 16, __half> h;
#pragma unroll
                for (int mi = 0; mi < 2; ++mi)
#pragma unroll
                    for (int ni = 0; ni < 2; ++ni) {
                        relu_to_half(acc[mi][ni], h);
                        wmma::store_matrix_sync(dst + (m0 + mi * 16) * KV_LD + n0 + ni * 16, h, KV_LD, wmma::mem_row_major);
                    }
            }
        }
        __syncthreads();

        // ---- kv[c][d] += k[c][:256] . v[d][:256] ----
#pragma unroll
        for (int kk = 0; kk < TNS / 16; ++kk) {
            wmma::fragment<wmma::matrix_a, 16, 16, 16, __half, wmma::row_major> af[2];
            wmma::fragment<wmma::matrix_b, 16, 16, 16, __half, wmma::col_major> bf[2];
#pragma unroll
            for (int mi = 0; mi < 2; ++mi)
                wmma::load_matrix_sync(af[mi], kf + (m0 + mi * 16) * KV_LD + kk * 16, KV_LD);
#pragma unroll
            for (int ni = 0; ni < 2; ++ni)
                wmma::load_matrix_sync(bf[ni], vf + (nw + ni * 16) * KV_LD + kk * 16, KV_LD);
#pragma unroll
            for (int mi = 0; mi < 2; ++mi)
#pragma unroll
                for (int ni = 0; ni < 2; ++ni) wmma::mma_sync(kvacc[mi][ni], af[mi], bf[ni], kvacc[mi][ni]);
        }
        __syncthreads();
    }

    float* part = g_kvpart[blockIdx.x];
#pragma unroll
    for (int mi = 0; mi < 2; ++mi)
#pragma unroll
        for (int ni = 0; ni < 2; ++ni)
            wmma::store_matrix_sync(part + (m0 + mi * 16) * C2 + nw + ni * 16, kvacc[mi][ni], C2, wmma::mem_row_major);
}

// ---------------- reduce kv partials + form M = (Wf . kv^T)/64 (64 blocks) ----------------
__global__ void mkernel(void) {
    __shared__ float kvs[16 * C2];
    const int b = blockIdx.x >> 3, slice = blockIdx.x & 7;
    const int tid = threadIdx.x;
    for (int i = tid; i < 16 * C2; i += 256) {
        int cl = i >> 7, d = i & 127;
        int c = slice * 16 + cl;
        float s = 0.f;
#pragma unroll
        for (int p = 0; p < 16; ++p) s += g_kvpart[b * 16 + p][c * C2 + d];
        kvs[i] = s;
    }
    __syncthreads();
    for (int i = tid; i < CO * 16; i += 256) {
        int o = i >> 4, cl = i & 15;
        float acc = 0.f;
#pragma unroll 8
        for (int d = 0; d < C2; ++d) acc = fmaf(g_Wf[o][d], kvs[cl * C2 + d], acc);
        g_M[b][o][slice * 16 + cl] = acc * (1.f / 64.f);
    }
}

// ---------------- pass 2 ----------------
__global__ void __launch_bounds__(512, 1) pass2_kernel(const float* __restrict__ x, float* __restrict__ out) {
    extern __shared__ char sm[];
    __half* xkn = (__half*)(sm + P2_XK);   // [k(80)][n(256)]
    __half* wq = (__half*)(sm + P2_WQ);    // [c][k]
    __half* qh = (__half*)(sm + P2_QH);    // [n(256)][c] ld Q_LD
    __half* mh = (__half*)(sm + P2_MH);    // [o][c] ld Q_LD
    float* scr = (float*)(sm + P2_SCR);    // [o][n(256)] ld SC_LD

    const int tid = threadIdx.x, w = tid >> 5;
    const int b = blockIdx.x >> 4, split = blockIdx.x & 15;
    const float* xb = x + (size_t)b * CIN * NN;
    const int mw = (w >> 2) * 32, nw = (w & 3) * 32;   // q GEMM warp tile
    const int o0 = (w & 3) * 16;                       // out GEMM warp tile

    for (int i = tid * 4; i < C2 * X_LD; i += 512 * 4)
        *reinterpret_cast<uint2*>(wq + i) = *reinterpret_cast<const uint2*>(g_Wqh + i);
    for (int i = tid; i < CO * C2; i += 512) {
        int o = i >> 7, c = i & 127;
        mh[o * Q_LD + c] = __float2half(g_M[b][o][c]);
    }
    for (int n = tid; n < TNS; n += 512) {
        xkn[CIN * XN_LD + n] = __float2half(1.0f);
#pragma unroll
        for (int k = CIN + 1; k < KP; ++k) xkn[k * XN_LD + n] = __float2half(0.0f);
    }

    for (int t = 0; t < 4; ++t) {
        const int nbase = split * 1024 + t * TNS;
        load_x_tile(xb, nbase, xkn, tid);
        __syncthreads();

        // ---- q : D[n][c]; A = x[n][k] col-major via xkn[k][n]; B = wq col-major ----
#pragma unroll
        for (int hn = 0; hn < 2; ++hn) {
            const int m0 = hn * 128 + mw;
            wmma::fragment<wmma::accumulator, 16, 16, 16, float> acc[2][2];
#pragma unroll
            for (int mi = 0; mi < 2; ++mi)
#pragma unroll
                for (int ni = 0; ni < 2; ++ni) wmma::fill_fragment(acc[mi][ni], 0.0f);
#pragma unroll
            for (int kk = 0; kk < KP / 16; ++kk) {
                wmma::fragment<wmma::matrix_a, 16, 16, 16, __half, wmma::col_major> af[2];
                wmma::fragment<wmma::matrix_b, 16, 16, 16, __half, wmma::col_major> bf[2];
#pragma unroll
                for (int mi = 0; mi < 2; ++mi)
                    wmma::load_matrix_sync(af[mi], xkn + kk * 16 * XN_LD + m0 + mi * 16, XN_LD);
#pragma unroll
                for (int ni = 0; ni < 2; ++ni)
                    wmma::load_matrix_sync(bf[ni], wq + (nw + ni * 16) * X_LD + kk * 16, X_LD);
#pragma unroll
                for (int mi = 0; mi < 2; ++mi)
#pragma unroll
                    for (int ni = 0; ni < 2; ++ni) wmma::mma_sync(acc[mi][ni], af[mi], bf[ni], acc[mi][ni]);
            }
            wmma::fragment<wmma::accumulator, 16, 16, 16, __half> h;
#pragma unroll
            for (int mi = 0; mi < 2; ++mi)
#pragma unroll
                for (int ni = 0; ni < 2; ++ni) {
                    relu_to_half(acc[mi][ni], h);
                    wmma::store_matrix_sync(qh + (m0 + mi * 16) * Q_LD + nw + ni * 16, h, Q_LD, wmma::mem_row_major);
                }
        }
        __syncthreads();

        // ---- out : D[n][o]; store transposed f32 scr[o][n] ----
#pragma unroll
        for (int hn = 0; hn < 2; ++hn) {
            const int m0 = hn * 128 + mw;
            wmma::fragment<wmma::accumulator, 16, 16, 16, float> acc[2];
#pragma unroll
            for (int mi = 0; mi < 2; ++mi) wmma::fill_fragment(acc[mi], 0.0f);
#pragma unroll
            for (int kk = 0; kk < 8; ++kk) {
                wmma::fragment<wmma::matrix_a, 16, 16, 16, __half, wmma::row_major> af[2];
                wmma::fragment<wmma::matrix_b, 16, 16, 16, __half, wmma::col_major> bf;
#pragma unroll
                for (int mi = 0; mi < 2; ++mi)
                    wmma::load_matrix_sync(af[mi], qh + (m0 + mi * 16) * Q_LD + kk * 16, Q_LD);
                wmma::load_matrix_sync(bf, mh + o0 * Q_LD + kk * 16, Q_LD);
#pragma unroll
                for (int mi = 0; mi < 2; ++mi) wmma::mma_sync(acc[mi], af[mi], bf, acc[mi]);
            }
#pragma unroll
            for (int mi = 0; mi < 2; ++mi)
                wmma::store_matrix_sync(scr + o0 * SC_LD + m0 + mi * 16, acc[mi], SC_LD, wmma::mem_col_major);
        }
        __syncthreads();

        // vectorized epilogue: float4 smem reads + float4 gmem stores
        for (int i = tid; i < CO * (TNS / 4); i += 512) {
            int o = i >> 6, n4 = (i & 63) << 2;
            float4 v = *reinterpret_cast<const float4*>(scr + o * SC_LD + n4);
            const float bias = g_bf[o];
            v.x = fmaxf(v.x * 64.f + bias, 0.f);
            v.y = fmaxf(v.y * 64.f + bias, 0.f);
            v.z = fmaxf(v.z * 64.f + bias, 0.f);
            v.w = fmaxf(v.w * 64.f + bias, 0.f);
            *reinterpret_cast<float4*>(out + (size_t)(b * CO + o) * NN + nbase + n4) = v;
        }
        __syncthreads();
    }
}

// ---------------- launch ----------------
extern "C" void kernel_launch(void* const* d_in, const int* in_sizes, int n_in,
                              void* d_out, int out_size) {
    const float* x   = (const float*)d_in[0];
    const float* Wq  = (const float*)d_in[1];
    const float* Wk  = (const float*)d_in[2];
    const float* Wv  = (const float*)d_in[3];
    const float* Wf  = (const float*)d_in[4];
    const float* bnq = (const float*)d_in[5];
    const float* bnk = (const float*)d_in[6];
    const float* bnv = (const float*)d_in[7];
    const float* bnf = (const float*)d_in[8];
    float* out = (float*)d_out;

    cudaFuncSetAttribute(pass1_kernel, cudaFuncAttributeMaxDynamicSharedMemorySize, P1_TOTAL);
    cudaFuncSetAttribute(pass2_kernel, cudaFuncAttributeMaxDynamicSharedMemorySize, P2_TOTAL);

    prep_kernel<<<1, 256>>>(Wq, Wk, Wv, Wf, bnq, bnk, bnv, bnf);
    pass1_kernel<<<P1_GRID, 512, P1_TOTAL>>>(x);
    mkernel<<<64, 256>>>();
    pass2_kernel<<<P2_GRID, 512, P2_TOTAL>>>(x, out);
}

// round 11
// speedup vs baseline: 5.4675x; 1.1493x over previous
#include <cuda_runtime.h>
#include <cuda_fp16.h>
#include <mma.h>
#include <cstdint>

using namespace nvcuda;

#define BB 8
#define CIN 67
#define C2 128
#define CO 64
#define NN 16384
#define EPSV 1e-5f

#define KP 80        // padded K (67 data + bias row 67 + zeros to 80)
#define X_LD 88      // weight smem leading dim (halfs), [o][k]
#define XN_LD 264    // xkn leading dim (256 n + 8), [k][n]
#define KV_LD 264    // kf/vf leading dim
#define Q_LD 136     // qh / mh leading dim (128 c + 8)
#define SC_LD 260    // f32 out scratch leading dim
#define TNS 256      // n super-tile
#define NV4 9        // ceil(CIN*TNS/4 / 512) float4 prefetches per thread
#define TOT4 (CIN * (TNS / 4))   // 4288

// pass1 smem byte offsets
#define P1_XK 0          // 80*264*2  = 42240
#define P1_WK 42240      // 22528
#define P1_WV 64768      // 22528
#define P1_KF 87296      // 67584
#define P1_VF 154880     // 67584
#define P1_TOTAL 222464
// pass2 smem byte offsets
#define P2_XK 0          // 42240
#define P2_WQ 42240      // 22528
#define P2_QH 64768      // 69632
#define P2_MH 134400     // 17408
#define P2_SCR 151808    // 66560
#define P2_TOTAL 218368

#define P1_GRID 128
#define P2_GRID 128

// ---------------- device scratch ----------------
__device__ __align__(16) __half g_Wqh[C2 * X_LD];
__device__ __align__(16) __half g_Wkh[C2 * X_LD];
__device__ __align__(16) __half g_Wvh[C2 * X_LD];
__device__ float g_Wf[CO][C2];
__device__ float g_bf[CO];
__device__ float g_M[BB][CO][C2];            // (Wf . kv^T) / 64
__device__ float g_kvpart[P1_GRID][C2 * C2];

template <typename FragF, typename FragH>
__device__ __forceinline__ void relu_to_half(const FragF& f, FragH& h) {
#pragma unroll
    for (int i = 0; i < f.num_elements; ++i)
        h.x[i] = __float2half(fmaxf(f.x[i], 0.0f));
}

// prologue-only direct load
__device__ __forceinline__ void load_x_tile(const float* __restrict__ xb, int nbase,
                                            __half* __restrict__ xkn, int tid) {
#pragma unroll
    for (int j = 0; j < NV4; ++j) {
        int i = tid + j * 512;
        if (i < TOT4) {
            int c = i >> 6, n4 = (i & 63) << 2;
            const float4 v = *reinterpret_cast<const float4*>(xb + (size_t)c * NN + nbase + n4);
            *reinterpret_cast<__half2*>(xkn + c * XN_LD + n4)     = __floats2half2_rn(v.x, v.y);
            *reinterpret_cast<__half2*>(xkn + c * XN_LD + n4 + 2) = __floats2half2_rn(v.z, v.w);
        }
    }
}

__device__ __forceinline__ void prefetch_regs(const float* __restrict__ xb, int nbase,
                                              float4* __restrict__ buf, int tid) {
#pragma unroll
    for (int j = 0; j < NV4; ++j) {
        int i = tid + j * 512;
        if (i < TOT4) {
            int c = i >> 6, n4 = (i & 63) << 2;
            buf[j] = *reinterpret_cast<const float4*>(xb + (size_t)c * NN + nbase + n4);
        }
    }
}

__device__ __forceinline__ void store_regs(const float4* __restrict__ buf,
                                           __half* __restrict__ xkn, int tid) {
#pragma unroll
    for (int j = 0; j < NV4; ++j) {
        int i = tid + j * 512;
        if (i < TOT4) {
            int c = i >> 6, n4 = (i & 63) << 2;
            *reinterpret_cast<__half2*>(xkn + c * XN_LD + n4)     = __floats2half2_rn(buf[j].x, buf[j].y);
            *reinterpret_cast<__half2*>(xkn + c * XN_LD + n4 + 2) = __floats2half2_rn(buf[j].z, buf[j].w);
        }
    }
}

// ---------------- prep (16 blocks) ----------------
__global__ void prep_kernel(const float* __restrict__ Wq, const float* __restrict__ Wk,
                            const float* __restrict__ Wv, const float* __restrict__ Wf,
                            const float* __restrict__ bnq, const float* __restrict__ bnk,
                            const float* __restrict__ bnv, const float* __restrict__ bnf) {
    __shared__ float sq[C2], sk[C2], sv[C2], shq[C2], shk[C2], shv[C2], sf[CO];
    int tid = threadIdx.x;
    if (tid < C2) {
        float s;
        s = bnq[tid] * rsqrtf(bnq[3 * C2 + tid] + EPSV); sq[tid] = s; shq[tid] = bnq[C2 + tid] - bnq[2 * C2 + tid] * s;
        s = bnk[tid] * rsqrtf(bnk[3 * C2 + tid] + EPSV); sk[tid] = s; shk[tid] = bnk[C2 + tid] - bnk[2 * C2 + tid] * s;
        s = bnv[tid] * rsqrtf(bnv[3 * C2 + tid] + EPSV); sv[tid] = s; shv[tid] = bnv[C2 + tid] - bnv[2 * C2 + tid] * s;
    }
    if (tid < CO) {
        float s = bnf[tid] * rsqrtf(bnf[3 * CO + tid] + EPSV);
        sf[tid] = s;
        if (blockIdx.x == 0) g_bf[tid] = bnf[CO + tid] - bnf[2 * CO + tid] * s;
    }
    __syncthreads();
    for (int i = blockIdx.x * 256 + tid; i < C2 * X_LD; i += gridDim.x * 256) {
        int o = i / X_LD, k = i % X_LD;
        float q = 0.f, kk = 0.f, v = 0.f;
        if (k < CIN) {
            q = Wq[o * CIN + k] * sq[o];
            kk = Wk[o * CIN + k] * sk[o];
            v = Wv[o * CIN + k] * sv[o];
        } else if (k == CIN) {
            q = shq[o]; kk = shk[o]; v = shv[o];
        }
        g_Wqh[i] = __float2half(q);
        g_Wkh[i] = __float2half(kk);
        g_Wvh[i] = __float2half(v);
    }
    for (int i = blockIdx.x * 256 + tid; i < CO * C2; i += gridDim.x * 256) {
        int o = i >> 7;
        g_Wf[0][i] = Wf[i] * sf[o];
    }
}

// ---------------- pass 1 (software-pipelined) ----------------
__global__ void __launch_bounds__(512, 1) pass1_kernel(const float* __restrict__ x) {
    extern __shared__ char sm[];
    __half* xkn = (__half*)(sm + P1_XK);   // [k(80)][n(256)]
    __half* wk = (__half*)(sm + P1_WK);
    __half* wv = (__half*)(sm + P1_WV);
    __half* kf = (__half*)(sm + P1_KF);    // [c][n] ld KV_LD
    __half* vf = (__half*)(sm + P1_VF);

    const int tid = threadIdx.x, w = tid >> 5;
    const int b = blockIdx.x >> 4, split = blockIdx.x & 15;
    const float* xb = x + (size_t)b * CIN * NN;
    const int m0 = (w >> 2) * 32, nw = (w & 3) * 32;

    for (int i = tid * 4; i < C2 * X_LD; i += 512 * 4) {
        *reinterpret_cast<uint2*>(wk + i) = *reinterpret_cast<const uint2*>(g_Wkh + i);
        *reinterpret_cast<uint2*>(wv + i) = *reinterpret_cast<const uint2*>(g_Wvh + i);
    }
    for (int n = tid; n < TNS; n += 512) {
        xkn[CIN * XN_LD + n] = __float2half(1.0f);
#pragma unroll
        for (int k = CIN + 1; k < KP; ++k) xkn[k * XN_LD + n] = __float2half(0.0f);
    }

    wmma::fragment<wmma::accumulator, 16, 16, 16, float> kvacc[2][2];
#pragma unroll
    for (int mi = 0; mi < 2; ++mi)
#pragma unroll
        for (int ni = 0; ni < 2; ++ni) wmma::fill_fragment(kvacc[mi][ni], 0.0f);

    load_x_tile(xb, split * 1024, xkn, tid);
    __syncthreads();

    for (int t = 0; t < 4; ++t) {
        // ---- phase A: k,v GEMMs -> kf, vf ----
#pragma unroll
        for (int which = 0; which < 2; ++which) {
            const __half* wsrc = which ? wv : wk;
            __half* dst = which ? vf : kf;
#pragma unroll
            for (int hn = 0; hn < 2; ++hn) {
                const int n0 = hn * 128 + nw;
                wmma::fragment<wmma::accumulator, 16, 16, 16, float> acc[2][2];
#pragma unroll
                for (int mi = 0; mi < 2; ++mi)
#pragma unroll
                    for (int ni = 0; ni < 2; ++ni) wmma::fill_fragment(acc[mi][ni], 0.0f);
#pragma unroll
                for (int kk = 0; kk < KP / 16; ++kk) {
                    wmma::fragment<wmma::matrix_a, 16, 16, 16, __half, wmma::row_major> af[2];
                    wmma::fragment<wmma::matrix_b, 16, 16, 16, __half, wmma::row_major> bf[2];
#pragma unroll
                    for (int mi = 0; mi < 2; ++mi)
                        wmma::load_matrix_sync(af[mi], wsrc + (m0 + mi * 16) * X_LD + kk * 16, X_LD);
#pragma unroll
                    for (int ni = 0; ni < 2; ++ni)
                        wmma::load_matrix_sync(bf[ni], xkn + kk * 16 * XN_LD + n0 + ni * 16, XN_LD);
#pragma unroll
                    for (int mi = 0; mi < 2; ++mi)
#pragma unroll
                        for (int ni = 0; ni < 2; ++ni) wmma::mma_sync(acc[mi][ni], af[mi], bf[ni], acc[mi][ni]);
                }
                wmma::fragment<wmma::accumulator, 16, 16, 16, __half> h;
#pragma unroll
                for (int mi = 0; mi < 2; ++mi)
#pragma unroll
                    for (int ni = 0; ni < 2; ++ni) {
                        relu_to_half(acc[mi][ni], h);
                        wmma::store_matrix_sync(dst + (m0 + mi * 16) * KV_LD + n0 + ni * 16, h, KV_LD, wmma::mem_row_major);
                    }
            }
        }
        __syncthreads();

        // ---- phase B: prefetch t+1 (regs) + kv-outer MMAs + store xkn ----
        float4 buf[NV4];
        if (t < 3) prefetch_regs(xb, split * 1024 + (t + 1) * TNS, buf, tid);

#pragma unroll
        for (int kk = 0; kk < TNS / 16; ++kk) {
            wmma::fragment<wmma::matrix_a, 16, 16, 16, __half, wmma::row_major> af[2];
            wmma::fragment<wmma::matrix_b, 16, 16, 16, __half, wmma::col_major> bf[2];
#pragma unroll
            for (int mi = 0; mi < 2; ++mi)
                wmma::load_matrix_sync(af[mi], kf + (m0 + mi * 16) * KV_LD + kk * 16, KV_LD);
#pragma unroll
            for (int ni = 0; ni < 2; ++ni)
                wmma::load_matrix_sync(bf[ni], vf + (nw + ni * 16) * KV_LD + kk * 16, KV_LD);
#pragma unroll
            for (int mi = 0; mi < 2; ++mi)
#pragma unroll
                for (int ni = 0; ni < 2; ++ni) wmma::mma_sync(kvacc[mi][ni], af[mi], bf[ni], kvacc[mi][ni]);
        }

        if (t < 3) store_regs(buf, xkn, tid);
        __syncthreads();
    }

    float* part = g_kvpart[blockIdx.x];
#pragma unroll
    for (int mi = 0; mi < 2; ++mi)
#pragma unroll
        for (int ni = 0; ni < 2; ++ni)
            wmma::store_matrix_sync(part + (m0 + mi * 16) * C2 + nw + ni * 16, kvacc[mi][ni], C2, wmma::mem_row_major);
}

// ---------------- reduce kv partials + form M = (Wf . kv^T)/64 ----------------
__global__ void mkernel(void) {
    __shared__ float kvs[16 * C2];
    const int b = blockIdx.x >> 3, slice = blockIdx.x & 7;
    const int tid = threadIdx.x;
    for (int i = tid; i < 16 * C2; i += 256) {
        int cl = i >> 7, d = i & 127;
        int c = slice * 16 + cl;
        float s = 0.f;
#pragma unroll
        for (int p = 0; p < 16; ++p) s += g_kvpart[b * 16 + p][c * C2 + d];
        kvs[i] = s;
    }
    __syncthreads();
    for (int i = tid; i < CO * 16; i += 256) {
        int o = i >> 4, cl = i & 15;
        float acc = 0.f;
#pragma unroll 8
        for (int d = 0; d < C2; ++d) acc = fmaf(g_Wf[o][d], kvs[cl * C2 + d], acc);
        g_M[b][o][slice * 16 + cl] = acc * (1.f / 64.f);
    }
}

// ---------------- pass 2 (software-pipelined, fused epilogue) ----------------
__device__ __forceinline__ void epilogue_store(const float* __restrict__ scr,
                                               float* __restrict__ out,
                                               int b, int nbase, int tid) {
#pragma unroll
    for (int j = 0; j < 8; ++j) {
        int i = tid + j * 512;   // CO*TNS/4 = 4096
        int o = i >> 6, n4 = (i & 63) << 2;
        float4 v = *reinterpret_cast<const float4*>(scr + o * SC_LD + n4);
        const float bias = g_bf[o];
        v.x = fmaxf(v.x * 64.f + bias, 0.f);
        v.y = fmaxf(v.y * 64.f + bias, 0.f);
        v.z = fmaxf(v.z * 64.f + bias, 0.f);
        v.w = fmaxf(v.w * 64.f + bias, 0.f);
        *reinterpret_cast<float4*>(out + (size_t)(b * CO + o) * NN + nbase + n4) = v;
    }
}

__global__ void __launch_bounds__(512, 1) pass2_kernel(const float* __restrict__ x, float* __restrict__ out) {
    extern __shared__ char sm[];
    __half* xkn = (__half*)(sm + P2_XK);
    __half* wq = (__half*)(sm + P2_WQ);
    __half* qh = (__half*)(sm + P2_QH);    // [n(256)][c] ld Q_LD
    __half* mh = (__half*)(sm + P2_MH);    // [o][c] ld Q_LD
    float* scr = (float*)(sm + P2_SCR);    // [o][n(256)] ld SC_LD

    const int tid = threadIdx.x, w = tid >> 5;
    const int b = blockIdx.x >> 4, split = blockIdx.x & 15;
    const float* xb = x + (size_t)b * CIN * NN;
    const int mw = (w >> 2) * 32, nw = (w & 3) * 32;
    const int o0 = (w & 3) * 16;

    for (int i = tid * 4; i < C2 * X_LD; i += 512 * 4)
        *reinterpret_cast<uint2*>(wq + i) = *reinterpret_cast<const uint2*>(g_Wqh + i);
    for (int i = tid; i < CO * C2; i += 512) {
        int o = i >> 7, c = i & 127;
        mh[o * Q_LD + c] = __float2half(g_M[b][o][c]);
    }
    for (int n = tid; n < TNS; n += 512) {
        xkn[CIN * XN_LD + n] = __float2half(1.0f);
#pragma unroll
        for (int k = CIN + 1; k < KP; ++k) xkn[k * XN_LD + n] = __float2half(0.0f);
    }

    load_x_tile(xb, split * 1024, xkn, tid);
    __syncthreads();

    for (int t = 0; t < 4; ++t) {
        const int nbase = split * 1024 + t * TNS;

        // ---- phase A: epilogue of t-1 + q GEMM -> qh ----
        if (t > 0) epilogue_store(scr, out, b, nbase - TNS, tid);
#pragma unroll
        for (int hn = 0; hn < 2; ++hn) {
            const int m0 = hn * 128 + mw;
            wmma::fragment<wmma::accumulator, 16, 16, 16, float> acc[2][2];
#pragma unroll
            for (int mi = 0; mi < 2; ++mi)
#pragma unroll
                for (int ni = 0; ni < 2; ++ni) wmma::fill_fragment(acc[mi][ni], 0.0f);
#pragma unroll
            for (int kk = 0; kk < KP / 16; ++kk) {
                wmma::fragment<wmma::matrix_a, 16, 16, 16, __half, wmma::col_major> af[2];
                wmma::fragment<wmma::matrix_b, 16, 16, 16, __half, wmma::col_major> bf[2];
#pragma unroll
                for (int mi = 0; mi < 2; ++mi)
                    wmma::load_matrix_sync(af[mi], xkn + kk * 16 * XN_LD + m0 + mi * 16, XN_LD);
#pragma unroll
                for (int ni = 0; ni < 2; ++ni)
                    wmma::load_matrix_sync(bf[ni], wq + (nw + ni * 16) * X_LD + kk * 16, X_LD);
#pragma unroll
                for (int mi = 0; mi < 2; ++mi)
#pragma unroll
                    for (int ni = 0; ni < 2; ++ni) wmma::mma_sync(acc[mi][ni], af[mi], bf[ni], acc[mi][ni]);
            }
            wmma::fragment<wmma::accumulator, 16, 16, 16, __half> h;
#pragma unroll
            for (int mi = 0; mi < 2; ++mi)
#pragma unroll
                for (int ni = 0; ni < 2; ++ni) {
                    relu_to_half(acc[mi][ni], h);
                    wmma::store_matrix_sync(qh + (m0 + mi * 16) * Q_LD + nw + ni * 16, h, Q_LD, wmma::mem_row_major);
                }
        }
        __syncthreads();

        // ---- phase B: prefetch t+1 + out GEMM -> scr + store xkn ----
        float4 buf[NV4];
        if (t < 3) prefetch_regs(xb, nbase + TNS, buf, tid);

#pragma unroll
        for (int hn = 0; hn < 2; ++hn) {
            const int m0 = hn * 128 + mw;
            wmma::fragment<wmma::accumulator, 16, 16, 16, float> acc[2];
#pragma unroll
            for (int mi = 0; mi < 2; ++mi) wmma::fill_fragment(acc[mi], 0.0f);
#pragma unroll
            for (int kk = 0; kk < 8; ++kk) {
                wmma::fragment<wmma::matrix_a, 16, 16, 16, __half, wmma::row_major> af[2];
                wmma::fragment<wmma::matrix_b, 16, 16, 16, __half, wmma::col_major> bf;
#pragma unroll
                for (int mi = 0; mi < 2; ++mi)
                    wmma::load_matrix_sync(af[mi], qh + (m0 + mi * 16) * Q_LD + kk * 16, Q_LD);
                wmma::load_matrix_sync(bf, mh + o0 * Q_LD + kk * 16, Q_LD);
#pragma unroll
                for (int mi = 0; mi < 2; ++mi) wmma::mma_sync(acc[mi], af[mi], bf, acc[mi]);
            }
#pragma unroll
            for (int mi = 0; mi < 2; ++mi)
                wmma::store_matrix_sync(scr + o0 * SC_LD + m0 + mi * 16, acc[mi], SC_LD, wmma::mem_col_major);
        }

        if (t < 3) store_regs(buf, xkn, tid);
        __syncthreads();
    }

    // final epilogue (tile 3)
    epilogue_store(scr, out, b, split * 1024 + 3 * TNS, tid);
}

// ---------------- launch ----------------
extern "C" void kernel_launch(void* const* d_in, const int* in_sizes, int n_in,
                              void* d_out, int out_size) {
    const float* x   = (const float*)d_in[0];
    const float* Wq  = (const float*)d_in[1];
    const float* Wk  = (const float*)d_in[2];
    const float* Wv  = (const float*)d_in[3];
    const float* Wf  = (const float*)d_in[4];
    const float* bnq = (const float*)d_in[5];
    const float* bnk = (const float*)d_in[6];
    const float* bnv = (const float*)d_in[7];
    const float* bnf = (const float*)d_in[8];
    float* out = (float*)d_out;

    cudaFuncSetAttribute(pass1_kernel, cudaFuncAttributeMaxDynamicSharedMemorySize, P1_TOTAL);
    cudaFuncSetAttribute(pass2_kernel, cudaFuncAttributeMaxDynamicSharedMemorySize, P2_TOTAL);

    prep_kernel<<<16, 256>>>(Wq, Wk, Wv, Wf, bnq, bnk, bnv, bnf);
    pass1_kernel<<<P1_GRID, 512, P1_TOTAL>>>(x);
    mkernel<<<64, 256>>>();
    pass2_kernel<<<P2_GRID, 512, P2_TOTAL>>>(x, out);
}